// round 11
// baseline (speedup 1.0000x reference)
#include <cuda_runtime.h>
#include <math.h>
#include <stdint.h>

// Problem constants (fixed-shape problem)
#define BATCH 32
#define SEQ   128
#define IDIM  1024
#define HDIM  1024
#define GDIM  4096   // 4*HDIM
#define VOCAB 32000

// ---------------- scratch (device globals; no cudaMalloc allowed) ----------------
__device__ float g_xg[SEQ * BATCH * GDIM];     // precomputed input gates (S,B,4H) : 64 MB
__device__ float g_h[BATCH * HDIM];            // current hidden state
__device__ float g_c[BATCH * HDIM];            // current cell state
__device__ float g_hs[SEQ * BATCH * HDIM];     // all hidden states (S,B,H) : 16 MB
__device__ float g_part[4 * BATCH * GDIM];     // K-split partial gate sums : 2 MB

// ---------------- packed f32x2 helpers (full-rate fp32 on sm_103a) ----------------
__device__ __forceinline__ unsigned long long pk2(float x) {
    unsigned long long r; unsigned u = __float_as_uint(x);
    asm("mov.b64 %0, {%1, %1};" : "=l"(r) : "r"(u));
    return r;
}
__device__ __forceinline__ unsigned long long pkab(float x, float y) {
    unsigned long long r;
    asm("mov.b64 %0, {%1, %2};" : "=l"(r) : "r"(__float_as_uint(x)), "r"(__float_as_uint(y)));
    return r;
}
__device__ __forceinline__ void fma2(unsigned long long& d, unsigned long long a, unsigned long long b) {
    asm("fma.rn.f32x2 %0, %1, %2, %0;" : "+l"(d) : "l"(a), "l"(b));
}
__device__ __forceinline__ float2 up2(unsigned long long v) {
    unsigned lo, hi;
    asm("mov.b64 {%0, %1}, %2;" : "=r"(lo), "=r"(hi) : "l"(v));
    return make_float2(__uint_as_float(lo), __uint_as_float(hi));
}

__device__ __forceinline__ float sigmoidf_(float x) { return 1.0f / (1.0f + expf(-x)); }

// ===================================================================================
// Kernel Z: zero h/c state (needed every replay; d_out/globals persist across replays)
// ===================================================================================
__global__ void k_zero() {
    int i = blockIdx.x * blockDim.x + threadIdx.x;
    if (i < BATCH * HDIM) { g_h[i] = 0.0f; g_c[i] = 0.0f; }
}

// ===================================================================================
// Kernel A: x_gates = gather(emb, ids) @ w_ih^T + b_ih + b_hh
//   GEMM NT: M=4096 (m = s*32+b), N=4096, K=1024. 128x128x8 tiles, 256 thr, 8x8/thr.
// ===================================================================================
__global__ __launch_bounds__(256) void k_xgates(
    const int* __restrict__ ids, const float* __restrict__ emb,
    const float* __restrict__ w_ih, const float* __restrict__ b_ih,
    const float* __restrict__ b_hh)
{
    __shared__ float As[8][128];
    __shared__ float Bs[8][128];

    const int t    = threadIdx.x;
    const int lrow = t >> 1;
    const int koff = (t & 1) * 4;
    const int m0   = blockIdx.y * 128;
    const int n0   = blockIdx.x * 128;

    // gather: global row m -> (s, b); id = input_ids[b*SEQ + s]
    const int m = m0 + lrow;
    const int s = m >> 5;
    const int b = m & 31;
    const float* arow = emb  + (size_t)ids[b * SEQ + s] * IDIM;
    const float* brow = w_ih + (size_t)(n0 + lrow) * IDIM;

    const int ty = t >> 4, tx = t & 15;
    const int rm = ty * 4;   // rows rm..rm+3 and rm+64..rm+67
    const int cn = tx * 4;   // cols cn..cn+3 and cn+64..cn+67

    unsigned long long acc[8][4];
#pragma unroll
    for (int i = 0; i < 8; i++)
#pragma unroll
        for (int j = 0; j < 4; j++) acc[i][j] = 0ull;

    for (int k0 = 0; k0 < IDIM; k0 += 8) {
        float4 av = *(const float4*)(arow + k0 + koff);
        float4 bv = *(const float4*)(brow + k0 + koff);
        __syncthreads();
        As[koff + 0][lrow] = av.x; As[koff + 1][lrow] = av.y;
        As[koff + 2][lrow] = av.z; As[koff + 3][lrow] = av.w;
        Bs[koff + 0][lrow] = bv.x; Bs[koff + 1][lrow] = bv.y;
        Bs[koff + 2][lrow] = bv.z; Bs[koff + 3][lrow] = bv.w;
        __syncthreads();
#pragma unroll
        for (int k = 0; k < 8; k++) {
            float4 a0 = *(const float4*)&As[k][rm];
            float4 a1 = *(const float4*)&As[k][rm + 64];
            float4 b0 = *(const float4*)&Bs[k][cn];
            float4 b1 = *(const float4*)&Bs[k][cn + 64];
            unsigned long long ap[8], bp[4];
            ap[0] = pk2(a0.x); ap[1] = pk2(a0.y); ap[2] = pk2(a0.z); ap[3] = pk2(a0.w);
            ap[4] = pk2(a1.x); ap[5] = pk2(a1.y); ap[6] = pk2(a1.z); ap[7] = pk2(a1.w);
            bp[0] = pkab(b0.x, b0.y); bp[1] = pkab(b0.z, b0.w);
            bp[2] = pkab(b1.x, b1.y); bp[3] = pkab(b1.z, b1.w);
#pragma unroll
            for (int i = 0; i < 8; i++)
#pragma unroll
                for (int j = 0; j < 4; j++) fma2(acc[i][j], ap[i], bp[j]);
        }
    }

    // bias
    float bi[8];
#pragma unroll
    for (int j = 0; j < 4; j++) {
        bi[j]     = b_ih[n0 + cn + j]      + b_hh[n0 + cn + j];
        bi[4 + j] = b_ih[n0 + cn + 64 + j] + b_hh[n0 + cn + 64 + j];
    }

#pragma unroll
    for (int i = 0; i < 8; i++) {
        int row = m0 + ((i < 4) ? (rm + i) : (64 + rm + i - 4));
        float* dst = g_xg + (size_t)row * GDIM + n0;
        float2 f0 = up2(acc[i][0]), f1 = up2(acc[i][1]);
        float2 f2 = up2(acc[i][2]), f3 = up2(acc[i][3]);
        *(float4*)(dst + cn)      = make_float4(f0.x + bi[0], f0.y + bi[1], f1.x + bi[2], f1.y + bi[3]);
        *(float4*)(dst + cn + 64) = make_float4(f2.x + bi[4], f2.y + bi[5], f3.x + bi[6], f3.y + bi[7]);
    }
}

// ===================================================================================
// Kernel B1: per-step recurrent partial GEMM.
//   part[p][b][r] = sum_{k in chunk p (256 wide)} h[b][k] * w_hh[r][k]
//   Grid (32 r-tiles of 128, 4 k-chunks) x 128 threads. Thread tile 4(b) x 8(r).
// ===================================================================================
__global__ __launch_bounds__(128) void k_gates(const float* __restrict__ w_hh)
{
    __shared__ float Hs[16][32];
    __shared__ float Ws[16][128];

    const int t      = threadIdx.x;
    const int rbase  = blockIdx.x * 128;
    const int p      = blockIdx.y;
    const int kstart = p * 256;

    // H load map: one float4 per thread per iter
    const int hb = t >> 2;          // 0..31 (batch row)
    const int hk = (t & 3) * 4;     // 0,4,8,12

    // W load map: 4 float4 per thread per iter (precomputable)
    int wrow[4], wk4[4];
#pragma unroll
    for (int q = 0; q < 4; q++) {
        int idx = q * 128 + t;
        wrow[q] = idx >> 2;
        wk4[q]  = (idx & 3) * 4;
    }

    const int tm  = t & 7;    // batch group
    const int tn  = t >> 3;   // 0..15 (r group)
    const int rb4 = tm * 4;
    const int rc8 = tn * 8;

    unsigned long long acc[4][4];
#pragma unroll
    for (int i = 0; i < 4; i++)
#pragma unroll
        for (int j = 0; j < 4; j++) acc[i][j] = 0ull;

    for (int kt = 0; kt < 256; kt += 16) {
        const int kb = kstart + kt;
        float4 hv = *(const float4*)(g_h + (size_t)hb * HDIM + kb + hk);
        float4 wv[4];
#pragma unroll
        for (int q = 0; q < 4; q++)
            wv[q] = *(const float4*)(w_hh + (size_t)(rbase + wrow[q]) * HDIM + kb + wk4[q]);

        __syncthreads();
        Hs[hk + 0][hb] = hv.x; Hs[hk + 1][hb] = hv.y;
        Hs[hk + 2][hb] = hv.z; Hs[hk + 3][hb] = hv.w;
#pragma unroll
        for (int q = 0; q < 4; q++) {
            Ws[wk4[q] + 0][wrow[q]] = wv[q].x; Ws[wk4[q] + 1][wrow[q]] = wv[q].y;
            Ws[wk4[q] + 2][wrow[q]] = wv[q].z; Ws[wk4[q] + 3][wrow[q]] = wv[q].w;
        }
        __syncthreads();

#pragma unroll
        for (int k = 0; k < 16; k++) {
            float4 ha = *(const float4*)&Hs[k][rb4];
            float4 w0 = *(const float4*)&Ws[k][rc8];
            float4 w1 = *(const float4*)&Ws[k][rc8 + 4];
            unsigned long long a0 = pk2(ha.x), a1 = pk2(ha.y), a2 = pk2(ha.z), a3 = pk2(ha.w);
            unsigned long long b0 = pkab(w0.x, w0.y), b1 = pkab(w0.z, w0.w);
            unsigned long long b2 = pkab(w1.x, w1.y), b3 = pkab(w1.z, w1.w);
            fma2(acc[0][0], a0, b0); fma2(acc[0][1], a0, b1); fma2(acc[0][2], a0, b2); fma2(acc[0][3], a0, b3);
            fma2(acc[1][0], a1, b0); fma2(acc[1][1], a1, b1); fma2(acc[1][2], a1, b2); fma2(acc[1][3], a1, b3);
            fma2(acc[2][0], a2, b0); fma2(acc[2][1], a2, b1); fma2(acc[2][2], a2, b2); fma2(acc[2][3], a2, b3);
            fma2(acc[3][0], a3, b0); fma2(acc[3][1], a3, b1); fma2(acc[3][2], a3, b2); fma2(acc[3][3], a3, b3);
        }
    }

#pragma unroll
    for (int i = 0; i < 4; i++) {
        const int b = rb4 + i;
        float* dst = g_part + ((size_t)(p * BATCH) + b) * GDIM + rbase + rc8;
        float2 f0 = up2(acc[i][0]), f1 = up2(acc[i][1]);
        float2 f2 = up2(acc[i][2]), f3 = up2(acc[i][3]);
        *(float4*)(dst)     = make_float4(f0.x, f0.y, f1.x, f1.y);
        *(float4*)(dst + 4) = make_float4(f2.x, f2.y, f3.x, f3.y);
    }
}

// ===================================================================================
// Kernel B2: per-step gate nonlinearity + state update.
//   gates = xg[s] + sum_p part[p]; i,f,o = sigmoid; g = tanh; c,h update; store hs[s].
// ===================================================================================
__global__ __launch_bounds__(256) void k_update(int s)
{
    const int idx = blockIdx.x * blockDim.x + threadIdx.x;   // < 32768
    const int b = idx >> 10;
    const int j = idx & 1023;

    const float* xb = g_xg + ((size_t)s * BATCH + b) * GDIM;

    float v[4];
#pragma unroll
    for (int q = 0; q < 4; q++) {
        float acc = xb[q * 1024 + j];
#pragma unroll
        for (int p = 0; p < 4; p++)
            acc += g_part[((size_t)(p * BATCH) + b) * GDIM + q * 1024 + j];
        v[q] = acc;
    }

    const float iv = sigmoidf_(v[0]);
    const float fv = sigmoidf_(v[1]);
    const float gv = tanhf(v[2]);
    const float ov = sigmoidf_(v[3]);

    const float cc = fv * g_c[idx] + iv * gv;
    const float hh = ov * tanhf(cc);

    g_c[idx] = cc;
    g_h[idx] = hh;
    g_hs[((size_t)s * BATCH + b) * HDIM + j] = hh;
}

// ===================================================================================
// Kernel C: output projection.  out[m][v] = hs_row(m) . w_out[v] + b_out[v]
//   m -> b = m / rows_per_b, s = ctx + m % rows_per_b.  GEMM NT M=2816,N=32000,K=1024.
// ===================================================================================
__global__ __launch_bounds__(256) void k_out(
    const float* __restrict__ w_out, const float* __restrict__ b_out,
    float* __restrict__ out, int ctx, int rows_per_b, int rows)
{
    __shared__ float As[8][128];
    __shared__ float Bs[8][128];

    const int t    = threadIdx.x;
    const int lrow = t >> 1;
    const int koff = (t & 1) * 4;
    const int m0   = blockIdx.y * 128;
    const int n0   = blockIdx.x * 128;

    const int m  = m0 + lrow;
    const int mc = (m < rows) ? m : (rows - 1);
    const int b  = mc / rows_per_b;
    const int sr = ctx + (mc % rows_per_b);
    const float* arow = g_hs  + ((size_t)sr * BATCH + b) * HDIM;
    const float* brow = w_out + (size_t)(n0 + lrow) * HDIM;

    const int ty = t >> 4, tx = t & 15;
    const int rm = ty * 4;
    const int cn = tx * 4;

    unsigned long long acc[8][4];
#pragma unroll
    for (int i = 0; i < 8; i++)
#pragma unroll
        for (int j = 0; j < 4; j++) acc[i][j] = 0ull;

    for (int k0 = 0; k0 < HDIM; k0 += 8) {
        float4 av = *(const float4*)(arow + k0 + koff);
        float4 bv = *(const float4*)(brow + k0 + koff);
        __syncthreads();
        As[koff + 0][lrow] = av.x; As[koff + 1][lrow] = av.y;
        As[koff + 2][lrow] = av.z; As[koff + 3][lrow] = av.w;
        Bs[koff + 0][lrow] = bv.x; Bs[koff + 1][lrow] = bv.y;
        Bs[koff + 2][lrow] = bv.z; Bs[koff + 3][lrow] = bv.w;
        __syncthreads();
#pragma unroll
        for (int k = 0; k < 8; k++) {
            float4 a0 = *(const float4*)&As[k][rm];
            float4 a1 = *(const float4*)&As[k][rm + 64];
            float4 b0 = *(const float4*)&Bs[k][cn];
            float4 b1 = *(const float4*)&Bs[k][cn + 64];
            unsigned long long ap[8], bp[4];
            ap[0] = pk2(a0.x); ap[1] = pk2(a0.y); ap[2] = pk2(a0.z); ap[3] = pk2(a0.w);
            ap[4] = pk2(a1.x); ap[5] = pk2(a1.y); ap[6] = pk2(a1.z); ap[7] = pk2(a1.w);
            bp[0] = pkab(b0.x, b0.y); bp[1] = pkab(b0.z, b0.w);
            bp[2] = pkab(b1.x, b1.y); bp[3] = pkab(b1.z, b1.w);
#pragma unroll
            for (int i = 0; i < 8; i++)
#pragma unroll
                for (int j = 0; j < 4; j++) fma2(acc[i][j], ap[i], bp[j]);
        }
    }

    float bi[8];
#pragma unroll
    for (int j = 0; j < 4; j++) {
        bi[j]     = b_out[n0 + cn + j];
        bi[4 + j] = b_out[n0 + cn + 64 + j];
    }

#pragma unroll
    for (int i = 0; i < 8; i++) {
        int row = m0 + ((i < 4) ? (rm + i) : (64 + rm + i - 4));
        if (row < rows) {
            float* dst = out + (size_t)row * VOCAB + n0;
            float2 f0 = up2(acc[i][0]), f1 = up2(acc[i][1]);
            float2 f2 = up2(acc[i][2]), f3 = up2(acc[i][3]);
            *(float4*)(dst + cn)      = make_float4(f0.x + bi[0], f0.y + bi[1], f1.x + bi[2], f1.y + bi[3]);
            *(float4*)(dst + cn + 64) = make_float4(f2.x + bi[4], f2.y + bi[5], f3.x + bi[6], f3.y + bi[7]);
        }
    }
}

// ===================================================================================
// kernel_launch: zero state -> input GEMM -> 128 x (gates GEMM, update) -> output GEMM
// All on default stream (graph-capturable, no sync, no alloc).
// ===================================================================================
extern "C" void kernel_launch(void* const* d_in, const int* in_sizes, int n_in,
                              void* d_out, int out_size)
{
    const int*   ids   = (const int*)  d_in[0];
    const float* emb   = (const float*)d_in[1];
    const float* w_ih  = (const float*)d_in[2];
    const float* w_hh  = (const float*)d_in[3];
    const float* b_ih  = (const float*)d_in[4];
    const float* b_hh  = (const float*)d_in[5];
    const float* w_out = (const float*)d_in[6];
    const float* b_out = (const float*)d_in[7];
    float* out = (float*)d_out;

    // derive context length from output size (avoids device-scalar read)
    const int rows       = out_size / VOCAB;     // (S - ctx) * B
    const int rows_per_b = rows / BATCH;         // S - ctx
    const int ctx        = SEQ - rows_per_b;

    // 0) zero h/c state (must happen every call — state persists across graph replays)
    k_zero<<<128, 256>>>();

    // 1) x_gates = gather(emb) @ w_ih^T + b_ih + b_hh
    k_xgates<<<dim3(32, 32), 256>>>(ids, emb, w_ih, b_ih, b_hh);

    // 2) recurrent scan: 128 steps, 2 kernels each
    for (int s = 0; s < SEQ; s++) {
        k_gates<<<dim3(32, 4), 128>>>(w_hh);
        k_update<<<128, 256>>>(s);
    }

    // 3) output projection
    const int mtiles = (rows + 127) / 128;
    k_out<<<dim3(VOCAB / 128, mtiles), 256>>>(w_out, b_out, out, ctx, rows_per_b, rows);
}

// round 14
// speedup vs baseline: 1.5411x; 1.5411x over previous
#include <cuda_runtime.h>
#include <cuda_bf16.h>
#include <math.h>
#include <stdint.h>

// Problem constants (fixed-shape problem)
#define BATCH 32
#define SEQ   128
#define IDIM  1024
#define HDIM  1024
#define GDIM  4096   // 4*HDIM
#define VOCAB 32000

// ---------------- scratch (device globals; no cudaMalloc allowed) ----------------
__device__ float g_xg[SEQ * BATCH * GDIM];     // input gates (S,B,4H) : 64 MB
__device__ float g_h[BATCH * HDIM];            // current hidden state
__device__ float g_c[BATCH * HDIM];            // current cell state
__device__ float g_hs[SEQ * BATCH * HDIM];     // all hidden states (S,B,H) : 16 MB
__device__ float g_part[4 * BATCH * GDIM];     // K-split partial gate sums : 2 MB
__device__ float g_bsum[GDIM];                 // b_ih + b_hh

// bf16 hi/lo splits for tensor-core GEMMs
__device__ __align__(16) __nv_bfloat16 g_x_hi[SEQ * BATCH * IDIM];   // gathered emb rows
__device__ __align__(16) __nv_bfloat16 g_x_lo[SEQ * BATCH * IDIM];
__device__ __align__(16) __nv_bfloat16 g_wih_hi[GDIM * IDIM];
__device__ __align__(16) __nv_bfloat16 g_wih_lo[GDIM * IDIM];
__device__ __align__(16) __nv_bfloat16 g_wo_hi[VOCAB * HDIM];        // 65.5 MB
__device__ __align__(16) __nv_bfloat16 g_wo_lo[VOCAB * HDIM];        // 65.5 MB
__device__ __align__(16) __nv_bfloat16 g_a_hi[SEQ * BATCH * HDIM];   // gathered hs rows
__device__ __align__(16) __nv_bfloat16 g_a_lo[SEQ * BATCH * HDIM];

// ---------------- packed f32x2 helpers (for the SIMT recurrent GEMM) ----------------
__device__ __forceinline__ unsigned long long pk2(float x) {
    unsigned long long r; unsigned u = __float_as_uint(x);
    asm("mov.b64 %0, {%1, %1};" : "=l"(r) : "r"(u));
    return r;
}
__device__ __forceinline__ unsigned long long pkab(float x, float y) {
    unsigned long long r;
    asm("mov.b64 %0, {%1, %2};" : "=l"(r) : "r"(__float_as_uint(x)), "r"(__float_as_uint(y)));
    return r;
}
__device__ __forceinline__ void fma2(unsigned long long& d, unsigned long long a, unsigned long long b) {
    asm("fma.rn.f32x2 %0, %1, %2, %0;" : "+l"(d) : "l"(a), "l"(b));
}
__device__ __forceinline__ float2 up2(unsigned long long v) {
    unsigned lo, hi;
    asm("mov.b64 {%0, %1}, %2;" : "=r"(lo), "=r"(hi) : "l"(v));
    return make_float2(__uint_as_float(lo), __uint_as_float(hi));
}
__device__ __forceinline__ float sigmoidf_(float x) { return 1.0f / (1.0f + expf(-x)); }

__device__ __forceinline__ uint32_t smem_u32(const void* p) {
    uint32_t a;
    asm("{ .reg .u64 t; cvta.to.shared.u64 t, %1; cvt.u32.u64 %0, t; }" : "=r"(a) : "l"(p));
    return a;
}

// ---------------- mma.sync / ldmatrix / cp.async (plain sm_103-legal) ----------------
#define LDMX4(r, addr)                                                                \
    asm volatile("ldmatrix.sync.aligned.m8n8.x4.shared.b16 {%0,%1,%2,%3}, [%4];"      \
        : "=r"((r)[0]), "=r"((r)[1]), "=r"((r)[2]), "=r"((r)[3]) : "r"(addr))

#define MMA_BF16(c, a, b)                                                             \
    asm volatile("mma.sync.aligned.m16n8k16.row.col.f32.bf16.bf16.f32 "               \
        "{%0,%1,%2,%3}, {%4,%5,%6,%7}, {%8,%9}, {%0,%1,%2,%3};"                       \
        : "+f"((c)[0]), "+f"((c)[1]), "+f"((c)[2]), "+f"((c)[3])                      \
        : "r"((a)[0]), "r"((a)[1]), "r"((a)[2]), "r"((a)[3]),                         \
          "r"((b)[0]), "r"((b)[1]))

#define CP_ASYNC16(dst, src)                                                          \
    asm volatile("cp.async.cg.shared.global [%0], [%1], 16;" :: "r"(dst), "l"(src))

// ===================================================================================
// k_gemm_mma: C[m][n] = sum_k A[m][k]*B[n][k] + bias[n]  via bf16x3 on mma.sync.
//   CTA tile 128x128, BK=64, 256 threads (8 warps, warp tile 32x64).
//   smem per stage: Ahi|Alo|Bhi|Blo tiles, 128 rows x 144B (padded, conflict-free).
//   Double-buffered cp.async. 3 accumulation terms: hi*hi + hi*lo + lo*hi.
// ===================================================================================
#define BM 128
#define BN 128
#define BK 64
#define ROWB 144                        // padded row stride in bytes (72 halves)
#define TILEB (128 * ROWB)              // 18432
#define STAGEB (4 * TILEB)              // 73728
#define SMEM_MMA (2 * STAGEB)           // 147456
#define NKT (1024 / BK)                 // 16 k-tiles

__global__ __launch_bounds__(256, 1)
void k_gemm_mma(const __nv_bfloat16* __restrict__ Ahi, const __nv_bfloat16* __restrict__ Alo,
                const __nv_bfloat16* __restrict__ Bhi, const __nv_bfloat16* __restrict__ Blo,
                const float* __restrict__ bias, float* __restrict__ C, int ldc)
{
    extern __shared__ char smbuf[];
    const uint32_t sb = smem_u32(smbuf);
    const int t = threadIdx.x, lid = t & 31, wid = t >> 5;
    const int m0 = blockIdx.x * BM;
    const int n0 = blockIdx.y * BN;
    const int wm = wid & 3;             // 4 m-warps (32 rows each)
    const int wn = wid >> 2;            // 2 n-warps (64 cols each)

    // cp.async row/col map: idx = t + i*256 over 1024 -> row = idx>>3, col16 = idx&7
    const int ldrow = t >> 3;           // base row (i adds 32)
    const int ldc16 = t & 7;

    auto load_stage = [&](int kt, int stg) {
        const int kc = kt * BK;
        const uint32_t dbase = sb + stg * STAGEB;
#pragma unroll
        for (int T = 0; T < 4; T++) {
            const __nv_bfloat16* src = (T == 0) ? Ahi : (T == 1) ? Alo : (T == 2) ? Bhi : Blo;
            const int rbase = (T < 2) ? m0 : n0;
#pragma unroll
            for (int i = 0; i < 4; i++) {
                const int row = ldrow + i * 32;
                const uint32_t dst = dbase + T * TILEB + row * ROWB + ldc16 * 16;
                const void* g = src + (size_t)(rbase + row) * 1024 + kc + ldc16 * 8;
                CP_ASYNC16(dst, g);
            }
        }
        asm volatile("cp.async.commit_group;" ::: "memory");
    };

    // ldmatrix per-lane offsets (within a tile), valid for all k-chunks
    const int sel = lid >> 3, i8 = lid & 7;
    uint32_t a_off[2], b_off[4];
#pragma unroll
    for (int mf = 0; mf < 2; mf++)
        a_off[mf] = (uint32_t)((wm * 32 + mf * 16 + (sel & 1) * 8 + i8) * ROWB + (sel >> 1) * 16);
#pragma unroll
    for (int g = 0; g < 4; g++)
        b_off[g] = (uint32_t)((wn * 64 + g * 16 + (sel >> 1) * 8 + i8) * ROWB + (sel & 1) * 16);

    float acc[2][8][4];
#pragma unroll
    for (int mf = 0; mf < 2; mf++)
#pragma unroll
        for (int nf = 0; nf < 8; nf++)
#pragma unroll
            for (int q = 0; q < 4; q++) acc[mf][nf][q] = 0.0f;

    load_stage(0, 0);

    for (int kt = 0; kt < NKT; kt++) {
        if (kt + 1 < NKT) {
            load_stage(kt + 1, (kt + 1) & 1);
            asm volatile("cp.async.wait_group 1;" ::: "memory");
        } else {
            asm volatile("cp.async.wait_group 0;" ::: "memory");
        }
        __syncthreads();

        const uint32_t ahb = sb + (kt & 1) * STAGEB;
        const uint32_t alb = ahb + TILEB;
        const uint32_t bhb = ahb + 2 * TILEB;
        const uint32_t blb = ahb + 3 * TILEB;

#pragma unroll
        for (int kk = 0; kk < 4; kk++) {
            const uint32_t kb = kk * 32;          // 16 halves per k-chunk
            uint32_t ah[2][4], al[2][4];
#pragma unroll
            for (int mf = 0; mf < 2; mf++) {
                LDMX4(ah[mf], ahb + a_off[mf] + kb);
                LDMX4(al[mf], alb + a_off[mf] + kb);
            }
            uint32_t bh[8][2], bl[8][2];
#pragma unroll
            for (int g = 0; g < 4; g++) {
                uint32_t r[4];
                LDMX4(r, bhb + b_off[g] + kb);
                bh[2 * g][0] = r[0]; bh[2 * g][1] = r[1];
                bh[2 * g + 1][0] = r[2]; bh[2 * g + 1][1] = r[3];
                LDMX4(r, blb + b_off[g] + kb);
                bl[2 * g][0] = r[0]; bl[2 * g][1] = r[1];
                bl[2 * g + 1][0] = r[2]; bl[2 * g + 1][1] = r[3];
            }
#pragma unroll
            for (int mf = 0; mf < 2; mf++)
#pragma unroll
                for (int nf = 0; nf < 8; nf++) {
                    MMA_BF16(acc[mf][nf], ah[mf], bh[nf]);
                    MMA_BF16(acc[mf][nf], ah[mf], bl[nf]);
                    MMA_BF16(acc[mf][nf], al[mf], bh[nf]);
                }
        }
        __syncthreads();
    }

    // epilogue: direct fragment writes (+bias)
#pragma unroll
    for (int mf = 0; mf < 2; mf++) {
        const int r0 = m0 + wm * 32 + mf * 16 + (lid >> 2);
#pragma unroll
        for (int nf = 0; nf < 8; nf++) {
            const int col = n0 + wn * 64 + nf * 8 + (lid & 3) * 2;
            const float b0 = bias[col], b1 = bias[col + 1];
            float2 v0 = make_float2(acc[mf][nf][0] + b0, acc[mf][nf][1] + b1);
            float2 v1 = make_float2(acc[mf][nf][2] + b0, acc[mf][nf][3] + b1);
            *(float2*)&C[(size_t)r0 * ldc + col]       = v0;
            *(float2*)&C[(size_t)(r0 + 8) * ldc + col] = v1;
        }
    }
}

// ===================================================================================
// Split / gather / bias kernels (bf16 hi-lo decomposition)
// ===================================================================================
__device__ __forceinline__ void split4(float4 v, __nv_bfloat16* hi, __nv_bfloat16* lo) {
    __nv_bfloat16 h0 = __float2bfloat16(v.x), h1 = __float2bfloat16(v.y);
    __nv_bfloat16 h2 = __float2bfloat16(v.z), h3 = __float2bfloat16(v.w);
    __nv_bfloat16 l0 = __float2bfloat16(v.x - __bfloat162float(h0));
    __nv_bfloat16 l1 = __float2bfloat16(v.y - __bfloat162float(h1));
    __nv_bfloat16 l2 = __float2bfloat16(v.z - __bfloat162float(h2));
    __nv_bfloat16 l3 = __float2bfloat16(v.w - __bfloat162float(h3));
    ((__nv_bfloat162*)hi)[0] = __halves2bfloat162(h0, h1);
    ((__nv_bfloat162*)hi)[1] = __halves2bfloat162(h2, h3);
    ((__nv_bfloat162*)lo)[0] = __halves2bfloat162(l0, l1);
    ((__nv_bfloat162*)lo)[1] = __halves2bfloat162(l2, l3);
}

__global__ void k_split(const float* __restrict__ src, __nv_bfloat16* __restrict__ hi,
                        __nv_bfloat16* __restrict__ lo, int n4)
{
    int i = blockIdx.x * blockDim.x + threadIdx.x;
    if (i >= n4) return;
    split4(((const float4*)src)[i], hi + i * 4, lo + i * 4);
}

// gather emb row per (s,b) GEMM row m = s*32+b, split to g_x_hi/lo
__global__ void k_split_gx(const int* __restrict__ ids, const float* __restrict__ emb)
{
    int m = blockIdx.x, t = threadIdx.x;        // 4096 blocks x 256 threads (4 elems each)
    int s = m >> 5, b = m & 31;
    const float* src = emb + (size_t)ids[b * SEQ + s] * IDIM;
    float4 v = ((const float4*)src)[t];
    split4(v, g_x_hi + (size_t)m * IDIM + t * 4, g_x_lo + (size_t)m * IDIM + t * 4);
}

// gather hs row per output row r (b-major), split to g_a_hi/lo
__global__ void k_split_gh(int ctx, int rpb)
{
    int r = blockIdx.x, t = threadIdx.x;
    int b = r / rpb, s = ctx + (r % rpb);
    const float* src = g_hs + ((size_t)s * BATCH + b) * HDIM;
    float4 v = ((const float4*)src)[t];
    split4(v, g_a_hi + (size_t)r * HDIM + t * 4, g_a_lo + (size_t)r * HDIM + t * 4);
}

__global__ void k_bsum(const float* __restrict__ b_ih, const float* __restrict__ b_hh)
{
    int i = blockIdx.x * blockDim.x + threadIdx.x;
    if (i < GDIM) g_bsum[i] = b_ih[i] + b_hh[i];
}

// ===================================================================================
// Kernel Z: zero h/c state (state persists across graph replays)
// ===================================================================================
__global__ void k_zero() {
    int i = blockIdx.x * blockDim.x + threadIdx.x;
    if (i < BATCH * HDIM) { g_h[i] = 0.0f; g_c[i] = 0.0f; }
}

// ===================================================================================
// Kernel B1: per-step recurrent partial GEMM (fp32 SIMT, unchanged)
// ===================================================================================
__global__ __launch_bounds__(128) void k_gates(const float* __restrict__ w_hh)
{
    __shared__ float Hs[16][32];
    __shared__ float Ws[16][128];

    const int t      = threadIdx.x;
    const int rbase  = blockIdx.x * 128;
    const int p      = blockIdx.y;
    const int kstart = p * 256;

    const int hb = t >> 2;
    const int hk = (t & 3) * 4;

    int wrow[4], wk4[4];
#pragma unroll
    for (int q = 0; q < 4; q++) {
        int idx = q * 128 + t;
        wrow[q] = idx >> 2;
        wk4[q]  = (idx & 3) * 4;
    }

    const int tm  = t & 7;
    const int tn  = t >> 3;
    const int rb4 = tm * 4;
    const int rc8 = tn * 8;

    unsigned long long acc[4][4];
#pragma unroll
    for (int i = 0; i < 4; i++)
#pragma unroll
        for (int j = 0; j < 4; j++) acc[i][j] = 0ull;

    for (int kt = 0; kt < 256; kt += 16) {
        const int kb = kstart + kt;
        float4 hv = *(const float4*)(g_h + (size_t)hb * HDIM + kb + hk);
        float4 wv[4];
#pragma unroll
        for (int q = 0; q < 4; q++)
            wv[q] = *(const float4*)(w_hh + (size_t)(rbase + wrow[q]) * HDIM + kb + wk4[q]);

        __syncthreads();
        Hs[hk + 0][hb] = hv.x; Hs[hk + 1][hb] = hv.y;
        Hs[hk + 2][hb] = hv.z; Hs[hk + 3][hb] = hv.w;
#pragma unroll
        for (int q = 0; q < 4; q++) {
            Ws[wk4[q] + 0][wrow[q]] = wv[q].x; Ws[wk4[q] + 1][wrow[q]] = wv[q].y;
            Ws[wk4[q] + 2][wrow[q]] = wv[q].z; Ws[wk4[q] + 3][wrow[q]] = wv[q].w;
        }
        __syncthreads();

#pragma unroll
        for (int k = 0; k < 16; k++) {
            float4 ha = *(const float4*)&Hs[k][rb4];
            float4 w0 = *(const float4*)&Ws[k][rc8];
            float4 w1 = *(const float4*)&Ws[k][rc8 + 4];
            unsigned long long a0 = pk2(ha.x), a1 = pk2(ha.y), a2 = pk2(ha.z), a3 = pk2(ha.w);
            unsigned long long b0 = pkab(w0.x, w0.y), b1 = pkab(w0.z, w0.w);
            unsigned long long b2 = pkab(w1.x, w1.y), b3 = pkab(w1.z, w1.w);
            fma2(acc[0][0], a0, b0); fma2(acc[0][1], a0, b1); fma2(acc[0][2], a0, b2); fma2(acc[0][3], a0, b3);
            fma2(acc[1][0], a1, b0); fma2(acc[1][1], a1, b1); fma2(acc[1][2], a1, b2); fma2(acc[1][3], a1, b3);
            fma2(acc[2][0], a2, b0); fma2(acc[2][1], a2, b1); fma2(acc[2][2], a2, b2); fma2(acc[2][3], a2, b3);
            fma2(acc[3][0], a3, b0); fma2(acc[3][1], a3, b1); fma2(acc[3][2], a3, b2); fma2(acc[3][3], a3, b3);
        }
    }

#pragma unroll
    for (int i = 0; i < 4; i++) {
        const int b = rb4 + i;
        float* dst = g_part + ((size_t)(p * BATCH) + b) * GDIM + rbase + rc8;
        float2 f0 = up2(acc[i][0]), f1 = up2(acc[i][1]);
        float2 f2 = up2(acc[i][2]), f3 = up2(acc[i][3]);
        *(float4*)(dst)     = make_float4(f0.x, f0.y, f1.x, f1.y);
        *(float4*)(dst + 4) = make_float4(f2.x, f2.y, f3.x, f3.y);
    }
}

// ===================================================================================
// Kernel B2: per-step gate nonlinearity + state update (unchanged)
// ===================================================================================
__global__ __launch_bounds__(256) void k_update(int s)
{
    const int idx = blockIdx.x * blockDim.x + threadIdx.x;
    const int b = idx >> 10;
    const int j = idx & 1023;

    const float* xb = g_xg + ((size_t)s * BATCH + b) * GDIM;

    float v[4];
#pragma unroll
    for (int q = 0; q < 4; q++) {
        float acc = xb[q * 1024 + j];
#pragma unroll
        for (int p = 0; p < 4; p++)
            acc += g_part[((size_t)(p * BATCH) + b) * GDIM + q * 1024 + j];
        v[q] = acc;
    }

    const float iv = sigmoidf_(v[0]);
    const float fv = sigmoidf_(v[1]);
    const float gv = tanhf(v[2]);
    const float ov = sigmoidf_(v[3]);

    const float cc = fv * g_c[idx] + iv * gv;
    const float hh = ov * tanhf(cc);

    g_c[idx] = cc;
    g_h[idx] = hh;
    g_hs[((size_t)s * BATCH + b) * HDIM + j] = hh;
}

// ===================================================================================
// kernel_launch
// ===================================================================================
extern "C" void kernel_launch(void* const* d_in, const int* in_sizes, int n_in,
                              void* d_out, int out_size)
{
    const int*   ids   = (const int*)  d_in[0];
    const float* emb   = (const float*)d_in[1];
    const float* w_ih  = (const float*)d_in[2];
    const float* w_hh  = (const float*)d_in[3];
    const float* b_ih  = (const float*)d_in[4];
    const float* b_hh  = (const float*)d_in[5];
    const float* w_out = (const float*)d_in[6];
    const float* b_out = (const float*)d_in[7];
    float* out = (float*)d_out;

    const int rows       = out_size / VOCAB;     // (S - ctx) * B = 2816
    const int rows_per_b = rows / BATCH;         // 88
    const int ctx        = SEQ - rows_per_b;     // 40

    cudaFuncSetAttribute(k_gemm_mma, cudaFuncAttributeMaxDynamicSharedMemorySize, SMEM_MMA);

    // device-pointer views of the split scratch
    __nv_bfloat16 *p_xhi, *p_xlo, *p_wihhi, *p_wihlo, *p_wohi, *p_wolo, *p_ahi, *p_alo;
    float *p_bsum, *p_xg;
    cudaGetSymbolAddress((void**)&p_xhi,   g_x_hi);
    cudaGetSymbolAddress((void**)&p_xlo,   g_x_lo);
    cudaGetSymbolAddress((void**)&p_wihhi, g_wih_hi);
    cudaGetSymbolAddress((void**)&p_wihlo, g_wih_lo);
    cudaGetSymbolAddress((void**)&p_wohi,  g_wo_hi);
    cudaGetSymbolAddress((void**)&p_wolo,  g_wo_lo);
    cudaGetSymbolAddress((void**)&p_ahi,   g_a_hi);
    cudaGetSymbolAddress((void**)&p_alo,   g_a_lo);
    cudaGetSymbolAddress((void**)&p_bsum,  g_bsum);
    cudaGetSymbolAddress((void**)&p_xg,    g_xg);

    // 0) state + biases + operand splits
    k_zero<<<128, 256>>>();
    k_bsum<<<16, 256>>>(b_ih, b_hh);
    k_split<<<(GDIM * IDIM / 4 + 255) / 256, 256>>>(w_ih, p_wihhi, p_wihlo, GDIM * IDIM / 4);
    k_split_gx<<<SEQ * BATCH, 256>>>(ids, emb);
    k_split<<<(VOCAB * HDIM / 4 + 255) / 256, 256>>>(w_out, p_wohi, p_wolo, VOCAB * HDIM / 4);

    // 1) x_gates = gather(emb) @ w_ih^T + (b_ih + b_hh)   — bf16x3 mma.sync
    k_gemm_mma<<<dim3(SEQ * BATCH / BM, GDIM / BN), 256, SMEM_MMA>>>(
        p_xhi, p_xlo, p_wihhi, p_wihlo, p_bsum, p_xg, GDIM);

    // 2) recurrent scan: 128 steps, 2 kernels each
    for (int s = 0; s < SEQ; s++) {
        k_gates<<<dim3(32, 4), 128>>>(w_hh);
        k_update<<<128, 256>>>(s);
    }

    // 3) gather+split hs rows, then output projection — bf16x3 mma.sync
    k_split_gh<<<rows, 256>>>(ctx, rows_per_b);
    k_gemm_mma<<<dim3(rows / BM, VOCAB / BN), 256, SMEM_MMA>>>(
        p_ahi, p_alo, p_wohi, p_wolo, b_out, out, VOCAB);
}

// round 15
// speedup vs baseline: 2.4713x; 1.6036x over previous
#include <cuda_runtime.h>
#include <cuda_bf16.h>
#include <math.h>
#include <stdint.h>

// Problem constants (fixed-shape problem)
#define BATCH 32
#define SEQ   128
#define IDIM  1024
#define HDIM  1024
#define GDIM  4096   // 4*HDIM
#define VOCAB 32000

// ---------------- scratch (device globals; no cudaMalloc allowed) ----------------
__device__ float g_xg[SEQ * BATCH * GDIM];     // input gates (S,B,4H) : 64 MB
__device__ float g_bsum[GDIM];                 // b_ih + b_hh
__device__ unsigned g_bar;                     // grid barrier counter

// h state, double-buffered by step parity, stored as bf16 hi/lo
__device__ __align__(16) __nv_bfloat16 g_hb_hi[2][BATCH * HDIM];
__device__ __align__(16) __nv_bfloat16 g_hb_lo[2][BATCH * HDIM];

// bf16 hi/lo splits for tensor-core GEMMs
__device__ __align__(16) __nv_bfloat16 g_x_hi[SEQ * BATCH * IDIM];   // gathered emb rows
__device__ __align__(16) __nv_bfloat16 g_x_lo[SEQ * BATCH * IDIM];
__device__ __align__(16) __nv_bfloat16 g_wih_hi[GDIM * IDIM];
__device__ __align__(16) __nv_bfloat16 g_wih_lo[GDIM * IDIM];
__device__ __align__(16) __nv_bfloat16 g_wo_hi[VOCAB * HDIM];        // 65.5 MB
__device__ __align__(16) __nv_bfloat16 g_wo_lo[VOCAB * HDIM];        // 65.5 MB
__device__ __align__(16) __nv_bfloat16 g_a_hi[SEQ * BATCH * HDIM];   // hs rows for k_out
__device__ __align__(16) __nv_bfloat16 g_a_lo[SEQ * BATCH * HDIM];

__device__ __forceinline__ float sigmoidf_(float x) { return 1.0f / (1.0f + expf(-x)); }

__device__ __forceinline__ uint32_t smem_u32(const void* p) {
    uint32_t a;
    asm("{ .reg .u64 t; cvta.to.shared.u64 t, %1; cvt.u32.u64 %0, t; }" : "=r"(a) : "l"(p));
    return a;
}
__device__ __forceinline__ unsigned ldacq(const unsigned* p) {
    unsigned v;
    asm volatile("ld.global.acquire.gpu.u32 %0, [%1];" : "=r"(v) : "l"(p));
    return v;
}

// ---------------- mma.sync / ldmatrix / cp.async (plain sm_103-legal) ----------------
#define LDMX4(r, addr)                                                                \
    asm volatile("ldmatrix.sync.aligned.m8n8.x4.shared.b16 {%0,%1,%2,%3}, [%4];"      \
        : "=r"((r)[0]), "=r"((r)[1]), "=r"((r)[2]), "=r"((r)[3]) : "r"(addr))

#define LDMX2(r, addr)                                                                \
    asm volatile("ldmatrix.sync.aligned.m8n8.x2.shared.b16 {%0,%1}, [%2];"            \
        : "=r"((r)[0]), "=r"((r)[1]) : "r"(addr))

#define MMA_BF16(c, a, b)                                                             \
    asm volatile("mma.sync.aligned.m16n8k16.row.col.f32.bf16.bf16.f32 "               \
        "{%0,%1,%2,%3}, {%4,%5,%6,%7}, {%8,%9}, {%0,%1,%2,%3};"                       \
        : "+f"((c)[0]), "+f"((c)[1]), "+f"((c)[2]), "+f"((c)[3])                      \
        : "r"((a)[0]), "r"((a)[1]), "r"((a)[2]), "r"((a)[3]),                         \
          "r"((b)[0]), "r"((b)[1]))

#define CP_ASYNC16(dst, src)                                                          \
    asm volatile("cp.async.cg.shared.global [%0], [%1], 16;" :: "r"(dst), "l"(src))

// ---------------- bf16 hi/lo split helper ----------------
__device__ __forceinline__ void split4(float4 v, __nv_bfloat16* hi, __nv_bfloat16* lo) {
    __nv_bfloat16 h0 = __float2bfloat16(v.x), h1 = __float2bfloat16(v.y);
    __nv_bfloat16 h2 = __float2bfloat16(v.z), h3 = __float2bfloat16(v.w);
    __nv_bfloat16 l0 = __float2bfloat16(v.x - __bfloat162float(h0));
    __nv_bfloat16 l1 = __float2bfloat16(v.y - __bfloat162float(h1));
    __nv_bfloat16 l2 = __float2bfloat16(v.z - __bfloat162float(h2));
    __nv_bfloat16 l3 = __float2bfloat16(v.w - __bfloat162float(h3));
    ((__nv_bfloat162*)hi)[0] = __halves2bfloat162(h0, h1);
    ((__nv_bfloat162*)hi)[1] = __halves2bfloat162(h2, h3);
    ((__nv_bfloat162*)lo)[0] = __halves2bfloat162(l0, l1);
    ((__nv_bfloat162*)lo)[1] = __halves2bfloat162(l2, l3);
}

// ===================================================================================
// k_gemm_mma: C[m][n] = sum_k A[m][k]*B[n][k] + bias[n]  via bf16x3 on mma.sync.
//   (unchanged from R14 — passing, proven addressing)
// ===================================================================================
#define BM 128
#define BN 128
#define BK 64
#define ROWB 144
#define TILEB (128 * ROWB)
#define STAGEB (4 * TILEB)
#define SMEM_MMA (2 * STAGEB)
#define NKT (1024 / BK)

__global__ __launch_bounds__(256, 1)
void k_gemm_mma(const __nv_bfloat16* __restrict__ Ahi, const __nv_bfloat16* __restrict__ Alo,
                const __nv_bfloat16* __restrict__ Bhi, const __nv_bfloat16* __restrict__ Blo,
                const float* __restrict__ bias, float* __restrict__ C, int ldc)
{
    extern __shared__ char smbuf[];
    const uint32_t sb = smem_u32(smbuf);
    const int t = threadIdx.x, lid = t & 31, wid = t >> 5;
    const int m0 = blockIdx.x * BM;
    const int n0 = blockIdx.y * BN;
    const int wm = wid & 3;
    const int wn = wid >> 2;

    const int ldrow = t >> 3;
    const int ldc16 = t & 7;

    auto load_stage = [&](int kt, int stg) {
        const int kc = kt * BK;
        const uint32_t dbase = sb + stg * STAGEB;
#pragma unroll
        for (int T = 0; T < 4; T++) {
            const __nv_bfloat16* src = (T == 0) ? Ahi : (T == 1) ? Alo : (T == 2) ? Bhi : Blo;
            const int rbase = (T < 2) ? m0 : n0;
#pragma unroll
            for (int i = 0; i < 4; i++) {
                const int row = ldrow + i * 32;
                const uint32_t dst = dbase + T * TILEB + row * ROWB + ldc16 * 16;
                const void* g = src + (size_t)(rbase + row) * 1024 + kc + ldc16 * 8;
                CP_ASYNC16(dst, g);
            }
        }
        asm volatile("cp.async.commit_group;" ::: "memory");
    };

    const int sel = lid >> 3, i8 = lid & 7;
    uint32_t a_off[2], b_off[4];
#pragma unroll
    for (int mf = 0; mf < 2; mf++)
        a_off[mf] = (uint32_t)((wm * 32 + mf * 16 + (sel & 1) * 8 + i8) * ROWB + (sel >> 1) * 16);
#pragma unroll
    for (int g = 0; g < 4; g++)
        b_off[g] = (uint32_t)((wn * 64 + g * 16 + (sel >> 1) * 8 + i8) * ROWB + (sel & 1) * 16);

    float acc[2][8][4];
#pragma unroll
    for (int mf = 0; mf < 2; mf++)
#pragma unroll
        for (int nf = 0; nf < 8; nf++)
#pragma unroll
            for (int q = 0; q < 4; q++) acc[mf][nf][q] = 0.0f;

    load_stage(0, 0);

    for (int kt = 0; kt < NKT; kt++) {
        if (kt + 1 < NKT) {
            load_stage(kt + 1, (kt + 1) & 1);
            asm volatile("cp.async.wait_group 1;" ::: "memory");
        } else {
            asm volatile("cp.async.wait_group 0;" ::: "memory");
        }
        __syncthreads();

        const uint32_t ahb = sb + (kt & 1) * STAGEB;
        const uint32_t alb = ahb + TILEB;
        const uint32_t bhb = ahb + 2 * TILEB;
        const uint32_t blb = ahb + 3 * TILEB;

#pragma unroll
        for (int kk = 0; kk < 4; kk++) {
            const uint32_t kb = kk * 32;
            uint32_t ah[2][4], al[2][4];
#pragma unroll
            for (int mf = 0; mf < 2; mf++) {
                LDMX4(ah[mf], ahb + a_off[mf] + kb);
                LDMX4(al[mf], alb + a_off[mf] + kb);
            }
            uint32_t bh[8][2], bl[8][2];
#pragma unroll
            for (int g = 0; g < 4; g++) {
                uint32_t r[4];
                LDMX4(r, bhb + b_off[g] + kb);
                bh[2 * g][0] = r[0]; bh[2 * g][1] = r[1];
                bh[2 * g + 1][0] = r[2]; bh[2 * g + 1][1] = r[3];
                LDMX4(r, blb + b_off[g] + kb);
                bl[2 * g][0] = r[0]; bl[2 * g][1] = r[1];
                bl[2 * g + 1][0] = r[2]; bl[2 * g + 1][1] = r[3];
            }
#pragma unroll
            for (int mf = 0; mf < 2; mf++)
#pragma unroll
                for (int nf = 0; nf < 8; nf++) {
                    MMA_BF16(acc[mf][nf], ah[mf], bh[nf]);
                    MMA_BF16(acc[mf][nf], ah[mf], bl[nf]);
                    MMA_BF16(acc[mf][nf], al[mf], bh[nf]);
                }
        }
        __syncthreads();
    }

#pragma unroll
    for (int mf = 0; mf < 2; mf++) {
        const int r0 = m0 + wm * 32 + mf * 16 + (lid >> 2);
#pragma unroll
        for (int nf = 0; nf < 8; nf++) {
            const int col = n0 + wn * 64 + nf * 8 + (lid & 3) * 2;
            const float b0 = bias[col], b1 = bias[col + 1];
            float2 v0 = make_float2(acc[mf][nf][0] + b0, acc[mf][nf][1] + b1);
            float2 v1 = make_float2(acc[mf][nf][2] + b0, acc[mf][nf][3] + b1);
            *(float2*)&C[(size_t)r0 * ldc + col]       = v0;
            *(float2*)&C[(size_t)(r0 + 8) * ldc + col] = v1;
        }
    }
}

// ===================================================================================
// k_scan: persistent fused LSTM scan. 128 CTAs (one per 8 hidden cols), 256 threads.
//   w_hh slice (32 gate rows) split bf16 hi/lo ONCE into smem, reused 128 steps.
//   Per step: gates = xg[s] + h @ w_hh^T (bf16x3 mma.sync, M=32 N=32 K=1024),
//   then gate nonlinearity + c/h update (c in registers), h written bf16 hi/lo to
//   parity-double-buffered gmem, grid barrier, next step.
// ===================================================================================
#define WSTR 2064                       // w row stride (2048+16; mod 128 == 16)
#define ASTR 528                        // h chunk row stride (512+16)
#define SM_WHI 0
#define SM_WLO 66048                    // 32*WSTR
#define SM_AB  132096                   // A chunk buffers: 2 x (hi 16896 + lo 16896)
#define SM_GTS 199680                   // gates 32x33 fp32
#define SMEM_SCAN 203904

__global__ __launch_bounds__(256, 1)
void k_scan(const float* __restrict__ w_hh, int ctx, int rpb)
{
    extern __shared__ char sm[];
    const uint32_t sb = smem_u32(sm);
    const int t = threadIdx.x, lid = t & 31, wid = t >> 5;
    const int cta = blockIdx.x;             // 0..127
    const int colbase = cta * 8;
    const int wm = wid & 1, wn = wid >> 1;  // 2 m16-tiles x 4 n8-tiles

    // ---- prologue: stage this CTA's 32 w_hh rows as bf16 hi/lo in smem
    // r_local = g*8 + jj  ->  global row = g*1024 + colbase + jj
    for (int idx = t; idx < 32 * 256; idx += 256) {
        const int r = idx >> 8, c4 = idx & 255;
        const int grow = (r >> 3) * 1024 + colbase + (r & 7);
        float4 v = *(const float4*)(w_hh + (size_t)grow * 1024 + c4 * 4);
        __nv_bfloat16 h4[4], l4[4];
        split4(v, h4, l4);
        *(uint2*)(sm + SM_WHI + r * WSTR + c4 * 8) = *(uint2*)h4;
        *(uint2*)(sm + SM_WLO + r * WSTR + c4 * 8) = *(uint2*)l4;
    }

    // zero h buffer 0 for this CTA's columns
    {
        const int b = t >> 3, jj = t & 7;
        g_hb_hi[0][b * 1024 + colbase + jj] = __float2bfloat16(0.0f);
        g_hb_lo[0][b * 1024 + colbase + jj] = __float2bfloat16(0.0f);
    }
    __threadfence();
    __syncthreads();
    if (t == 0) {
        atomicAdd(&g_bar, 1u);
        while (ldacq(&g_bar) < 128u) __nanosleep(32);
    }
    __syncthreads();

    // ldmatrix lane offsets
    const int sel = lid >> 3, i8 = lid & 7;
    const uint32_t a_loff = (uint32_t)((wm * 16 + (sel & 1) * 8 + i8) * ASTR + (sel >> 1) * 16);
    const int l16 = lid & 15;
    const uint32_t b_off = sb + (uint32_t)((wn * 8 + (l16 & 7)) * WSTR + (l16 >> 3) * 16);

    // update-thread mapping: one (batch, jj) pair per thread; c stays in register
    const int ub = t >> 3, ujj = t & 7;
    const int ucol = colbase + ujj;
    float creg = 0.0f;
    float* gates_s = (float*)(sm + SM_GTS);

    for (int s = 0; s < SEQ; s++) {
        const int p = s & 1, np = p ^ 1;
        const __nv_bfloat16* hhi = g_hb_hi[p];
        const __nv_bfloat16* hlo = g_hb_lo[p];

        auto loadc = [&](int ch) {
            const uint32_t abase = sb + SM_AB + (uint32_t)((ch & 1) * 33792);
#pragma unroll
            for (int i = 0; i < 4; i++) {
                const int idx = t + i * 256, row = idx >> 5, c16 = idx & 31;
                CP_ASYNC16(abase + row * ASTR + c16 * 16,
                           hhi + row * 1024 + ch * 256 + c16 * 8);
                CP_ASYNC16(abase + 16896u + row * ASTR + c16 * 16,
                           hlo + row * 1024 + ch * 256 + c16 * 8);
            }
            asm volatile("cp.async.commit_group;" ::: "memory");
        };

        float acc[4] = {0.0f, 0.0f, 0.0f, 0.0f};
        loadc(0);
        for (int ch = 0; ch < 4; ch++) {
            if (ch < 3) { loadc(ch + 1); asm volatile("cp.async.wait_group 1;" ::: "memory"); }
            else        {                asm volatile("cp.async.wait_group 0;" ::: "memory"); }
            __syncthreads();
            const uint32_t abh = sb + SM_AB + (uint32_t)((ch & 1) * 33792) + a_loff;
            const uint32_t abl = abh + 16896u;
            const uint32_t wk = (uint32_t)(ch * 512);
#pragma unroll
            for (int k16 = 0; k16 < 16; k16++) {
                uint32_t ah[4], al[4], bh[2], bl[2];
                LDMX4(ah, abh + k16 * 32);
                LDMX4(al, abl + k16 * 32);
                LDMX2(bh, b_off + wk + k16 * 32);
                LDMX2(bl, b_off + 66048u + wk + k16 * 32);
                MMA_BF16(acc, ah, bh);
                MMA_BF16(acc, ah, bl);
                MMA_BF16(acc, al, bh);
            }
            __syncthreads();
        }

        // write accumulators to gates_s[r_local][b] (stride 33)
        {
            const int m = wm * 16 + (lid >> 2);
            const int n = wn * 8 + (lid & 3) * 2;
            gates_s[n * 33 + m]             = acc[0];
            gates_s[(n + 1) * 33 + m]       = acc[1];
            gates_s[n * 33 + m + 8]         = acc[2];
            gates_s[(n + 1) * 33 + m + 8]   = acc[3];
        }
        __syncthreads();

        // gate nonlinearity + state update (thread owns (ub, ujj); c in register)
        {
            const float* xr = g_xg + (size_t)(s * 32 + ub) * GDIM + ucol;
            const float ipre = gates_s[(0  + ujj) * 33 + ub] + xr[0];
            const float fpre = gates_s[(8  + ujj) * 33 + ub] + xr[1024];
            const float gpre = gates_s[(16 + ujj) * 33 + ub] + xr[2048];
            const float opre = gates_s[(24 + ujj) * 33 + ub] + xr[3072];
            const float iv = sigmoidf_(ipre), fv = sigmoidf_(fpre);
            const float gv = tanhf(gpre),     ov = sigmoidf_(opre);
            creg = fv * creg + iv * gv;
            const float hv = ov * tanhf(creg);
            const __nv_bfloat16 hb = __float2bfloat16(hv);
            const __nv_bfloat16 lb = __float2bfloat16(hv - __bfloat162float(hb));
            g_hb_hi[np][ub * 1024 + ucol] = hb;
            g_hb_lo[np][ub * 1024 + ucol] = lb;
            if (s >= ctx) {
                const size_t ro = (size_t)(ub * rpb + (s - ctx)) * 1024 + ucol;
                g_a_hi[ro] = hb;
                g_a_lo[ro] = lb;
            }
        }
        __threadfence();
        __syncthreads();
        if (t == 0) {
            atomicAdd(&g_bar, 1u);
            const unsigned tgt = 128u * (unsigned)(s + 2);
            while (ldacq(&g_bar) < tgt) __nanosleep(32);
        }
        __syncthreads();
    }
}

// ===================================================================================
// Split / gather / bias / reset kernels
// ===================================================================================
__global__ void k_split(const float* __restrict__ src, __nv_bfloat16* __restrict__ hi,
                        __nv_bfloat16* __restrict__ lo, int n4)
{
    int i = blockIdx.x * blockDim.x + threadIdx.x;
    if (i >= n4) return;
    split4(((const float4*)src)[i], hi + i * 4, lo + i * 4);
}

__global__ void k_split_gx(const int* __restrict__ ids, const float* __restrict__ emb)
{
    int m = blockIdx.x, t = threadIdx.x;
    int s = m >> 5, b = m & 31;
    const float* src = emb + (size_t)ids[b * SEQ + s] * IDIM;
    float4 v = ((const float4*)src)[t];
    split4(v, g_x_hi + (size_t)m * IDIM + t * 4, g_x_lo + (size_t)m * IDIM + t * 4);
}

__global__ void k_bsum(const float* __restrict__ b_ih, const float* __restrict__ b_hh)
{
    int i = blockIdx.x * blockDim.x + threadIdx.x;
    if (i < GDIM) g_bsum[i] = b_ih[i] + b_hh[i];
}

__global__ void k_reset() {
    if (threadIdx.x == 0 && blockIdx.x == 0) g_bar = 0;
}

// ===================================================================================
// kernel_launch
// ===================================================================================
extern "C" void kernel_launch(void* const* d_in, const int* in_sizes, int n_in,
                              void* d_out, int out_size)
{
    const int*   ids   = (const int*)  d_in[0];
    const float* emb   = (const float*)d_in[1];
    const float* w_ih  = (const float*)d_in[2];
    const float* w_hh  = (const float*)d_in[3];
    const float* b_ih  = (const float*)d_in[4];
    const float* b_hh  = (const float*)d_in[5];
    const float* w_out = (const float*)d_in[6];
    const float* b_out = (const float*)d_in[7];
    float* out = (float*)d_out;

    const int rows       = out_size / VOCAB;     // (S - ctx) * B = 2816
    const int rows_per_b = rows / BATCH;         // 88
    const int ctx        = SEQ - rows_per_b;     // 40

    cudaFuncSetAttribute(k_gemm_mma, cudaFuncAttributeMaxDynamicSharedMemorySize, SMEM_MMA);
    cudaFuncSetAttribute(k_scan,     cudaFuncAttributeMaxDynamicSharedMemorySize, SMEM_SCAN);

    __nv_bfloat16 *p_xhi, *p_xlo, *p_wihhi, *p_wihlo, *p_wohi, *p_wolo, *p_ahi, *p_alo;
    float *p_bsum, *p_xg;
    cudaGetSymbolAddress((void**)&p_xhi,   g_x_hi);
    cudaGetSymbolAddress((void**)&p_xlo,   g_x_lo);
    cudaGetSymbolAddress((void**)&p_wihhi, g_wih_hi);
    cudaGetSymbolAddress((void**)&p_wihlo, g_wih_lo);
    cudaGetSymbolAddress((void**)&p_wohi,  g_wo_hi);
    cudaGetSymbolAddress((void**)&p_wolo,  g_wo_lo);
    cudaGetSymbolAddress((void**)&p_ahi,   g_a_hi);
    cudaGetSymbolAddress((void**)&p_alo,   g_a_lo);
    cudaGetSymbolAddress((void**)&p_bsum,  g_bsum);
    cudaGetSymbolAddress((void**)&p_xg,    g_xg);

    // 0) reset barrier + biases + operand splits
    k_reset<<<1, 32>>>();
    k_bsum<<<16, 256>>>(b_ih, b_hh);
    k_split<<<(GDIM * IDIM / 4 + 255) / 256, 256>>>(w_ih, p_wihhi, p_wihlo, GDIM * IDIM / 4);
    k_split_gx<<<SEQ * BATCH, 256>>>(ids, emb);
    k_split<<<(VOCAB * HDIM / 4 + 255) / 256, 256>>>(w_out, p_wohi, p_wolo, VOCAB * HDIM / 4);

    // 1) x_gates = gather(emb) @ w_ih^T + (b_ih + b_hh)   — bf16x3 mma.sync
    k_gemm_mma<<<dim3(SEQ * BATCH / BM, GDIM / BN), 256, SMEM_MMA>>>(
        p_xhi, p_xlo, p_wihhi, p_wihlo, p_bsum, p_xg, GDIM);

    // 2) fused persistent recurrent scan (replaces 256 per-step launches)
    k_scan<<<128, 256, SMEM_SCAN>>>(w_hh, ctx, rows_per_b);

    // 3) output projection — bf16x3 mma.sync (scan wrote a_hi/a_lo directly)
    k_gemm_mma<<<dim3(rows / BM, VOCAB / BN), 256, SMEM_MMA>>>(
        p_ahi, p_alo, p_wohi, p_wolo, b_out, out, VOCAB);
}

// round 16
// speedup vs baseline: 2.9225x; 1.1826x over previous
#include <cuda_runtime.h>
#include <cuda_bf16.h>
#include <cuda_fp16.h>
#include <math.h>
#include <stdint.h>

// Problem constants (fixed-shape problem)
#define BATCH 32
#define SEQ   128
#define IDIM  1024
#define HDIM  1024
#define GDIM  4096   // 4*HDIM
#define VOCAB 32000

// ---------------- scratch (device globals; no cudaMalloc allowed) ----------------
__device__ float g_xg[SEQ * BATCH * GDIM];     // input gates (S,B,4H) : 64 MB
__device__ float g_bsum[GDIM];                 // b_ih + b_hh
__device__ unsigned g_bar;                     // grid barrier counter

// h state, double-buffered by step parity, stored as bf16 hi/lo
__device__ __align__(16) __nv_bfloat16 g_hb_hi[2][BATCH * HDIM];
__device__ __align__(16) __nv_bfloat16 g_hb_lo[2][BATCH * HDIM];

// bf16 hi/lo splits for the input GEMM (bf16x3)
__device__ __align__(16) __nv_bfloat16 g_x_hi[SEQ * BATCH * IDIM];   // gathered emb rows
__device__ __align__(16) __nv_bfloat16 g_x_lo[SEQ * BATCH * IDIM];
__device__ __align__(16) __nv_bfloat16 g_wih_hi[GDIM * IDIM];
__device__ __align__(16) __nv_bfloat16 g_wih_lo[GDIM * IDIM];

// fp16 operands for the output GEMM (fp16 2-term: Ahi*(Bhi+Blo))
__device__ __align__(16) half g_wo_hi[VOCAB * HDIM];                 // 65.5 MB
__device__ __align__(16) half g_wo_lo[VOCAB * HDIM];                 // 65.5 MB
__device__ __align__(16) half g_af[SEQ * BATCH * HDIM];              // hs rows (fp16)

__device__ __forceinline__ float sigmoidf_(float x) { return 1.0f / (1.0f + expf(-x)); }

__device__ __forceinline__ uint32_t smem_u32(const void* p) {
    uint32_t a;
    asm("{ .reg .u64 t; cvta.to.shared.u64 t, %1; cvt.u32.u64 %0, t; }" : "=r"(a) : "l"(p));
    return a;
}
__device__ __forceinline__ unsigned ldacq(const unsigned* p) {
    unsigned v;
    asm volatile("ld.global.acquire.gpu.u32 %0, [%1];" : "=r"(v) : "l"(p));
    return v;
}

// ---------------- mma.sync / ldmatrix / cp.async (plain sm_103-legal) ----------------
#define LDMX4(r, addr)                                                                \
    asm volatile("ldmatrix.sync.aligned.m8n8.x4.shared.b16 {%0,%1,%2,%3}, [%4];"      \
        : "=r"((r)[0]), "=r"((r)[1]), "=r"((r)[2]), "=r"((r)[3]) : "r"(addr))

#define LDMX2(r, addr)                                                                \
    asm volatile("ldmatrix.sync.aligned.m8n8.x2.shared.b16 {%0,%1}, [%2];"            \
        : "=r"((r)[0]), "=r"((r)[1]) : "r"(addr))

#define MMA_BF16(c, a, b)                                                             \
    asm volatile("mma.sync.aligned.m16n8k16.row.col.f32.bf16.bf16.f32 "               \
        "{%0,%1,%2,%3}, {%4,%5,%6,%7}, {%8,%9}, {%0,%1,%2,%3};"                       \
        : "+f"((c)[0]), "+f"((c)[1]), "+f"((c)[2]), "+f"((c)[3])                      \
        : "r"((a)[0]), "r"((a)[1]), "r"((a)[2]), "r"((a)[3]),                         \
          "r"((b)[0]), "r"((b)[1]))

#define MMA_F16(c, a, b)                                                              \
    asm volatile("mma.sync.aligned.m16n8k16.row.col.f32.f16.f16.f32 "                 \
        "{%0,%1,%2,%3}, {%4,%5,%6,%7}, {%8,%9}, {%0,%1,%2,%3};"                       \
        : "+f"((c)[0]), "+f"((c)[1]), "+f"((c)[2]), "+f"((c)[3])                      \
        : "r"((a)[0]), "r"((a)[1]), "r"((a)[2]), "r"((a)[3]),                         \
          "r"((b)[0]), "r"((b)[1]))

#define CP_ASYNC16(dst, src)                                                          \
    asm volatile("cp.async.cg.shared.global [%0], [%1], 16;" :: "r"(dst), "l"(src))

// ---------------- bf16 hi/lo split helper ----------------
__device__ __forceinline__ void split4(float4 v, __nv_bfloat16* hi, __nv_bfloat16* lo) {
    __nv_bfloat16 h0 = __float2bfloat16(v.x), h1 = __float2bfloat16(v.y);
    __nv_bfloat16 h2 = __float2bfloat16(v.z), h3 = __float2bfloat16(v.w);
    __nv_bfloat16 l0 = __float2bfloat16(v.x - __bfloat162float(h0));
    __nv_bfloat16 l1 = __float2bfloat16(v.y - __bfloat162float(h1));
    __nv_bfloat16 l2 = __float2bfloat16(v.z - __bfloat162float(h2));
    __nv_bfloat16 l3 = __float2bfloat16(v.w - __bfloat162float(h3));
    ((__nv_bfloat162*)hi)[0] = __halves2bfloat162(h0, h1);
    ((__nv_bfloat162*)hi)[1] = __halves2bfloat162(h2, h3);
    ((__nv_bfloat162*)lo)[0] = __halves2bfloat162(l0, l1);
    ((__nv_bfloat162*)lo)[1] = __halves2bfloat162(l2, l3);
}

// fp16 hi/lo split helper
__device__ __forceinline__ void split4h(float4 v, half* hi, half* lo) {
    half h0 = __float2half(v.x), h1 = __float2half(v.y);
    half h2 = __float2half(v.z), h3 = __float2half(v.w);
    half l0 = __float2half(v.x - __half2float(h0));
    half l1 = __float2half(v.y - __half2float(h1));
    half l2 = __float2half(v.z - __half2float(h2));
    half l3 = __float2half(v.w - __half2float(h3));
    ((half2*)hi)[0] = __halves2half2(h0, h1);
    ((half2*)hi)[1] = __halves2half2(h2, h3);
    ((half2*)lo)[0] = __halves2half2(l0, l1);
    ((half2*)lo)[1] = __halves2half2(l2, l3);
}

// ===================================================================================
// k_gemm_mma: bf16x3 GEMM (unchanged, used for x_gates)
// ===================================================================================
#define BM 128
#define BN 128
#define BK 64
#define ROWB 144
#define TILEB (128 * ROWB)
#define STAGEB (4 * TILEB)
#define SMEM_MMA (2 * STAGEB)
#define NKT (1024 / BK)

__global__ __launch_bounds__(256, 1)
void k_gemm_mma(const __nv_bfloat16* __restrict__ Ahi, const __nv_bfloat16* __restrict__ Alo,
                const __nv_bfloat16* __restrict__ Bhi, const __nv_bfloat16* __restrict__ Blo,
                const float* __restrict__ bias, float* __restrict__ C, int ldc)
{
    extern __shared__ char smbuf[];
    const uint32_t sb = smem_u32(smbuf);
    const int t = threadIdx.x, lid = t & 31, wid = t >> 5;
    const int m0 = blockIdx.x * BM;
    const int n0 = blockIdx.y * BN;
    const int wm = wid & 3;
    const int wn = wid >> 2;

    const int ldrow = t >> 3;
    const int ldc16 = t & 7;

    auto load_stage = [&](int kt, int stg) {
        const int kc = kt * BK;
        const uint32_t dbase = sb + stg * STAGEB;
#pragma unroll
        for (int T = 0; T < 4; T++) {
            const __nv_bfloat16* src = (T == 0) ? Ahi : (T == 1) ? Alo : (T == 2) ? Bhi : Blo;
            const int rbase = (T < 2) ? m0 : n0;
#pragma unroll
            for (int i = 0; i < 4; i++) {
                const int row = ldrow + i * 32;
                const uint32_t dst = dbase + T * TILEB + row * ROWB + ldc16 * 16;
                const void* g = src + (size_t)(rbase + row) * 1024 + kc + ldc16 * 8;
                CP_ASYNC16(dst, g);
            }
        }
        asm volatile("cp.async.commit_group;" ::: "memory");
    };

    const int sel = lid >> 3, i8 = lid & 7;
    uint32_t a_off[2], b_off[4];
#pragma unroll
    for (int mf = 0; mf < 2; mf++)
        a_off[mf] = (uint32_t)((wm * 32 + mf * 16 + (sel & 1) * 8 + i8) * ROWB + (sel >> 1) * 16);
#pragma unroll
    for (int g = 0; g < 4; g++)
        b_off[g] = (uint32_t)((wn * 64 + g * 16 + (sel >> 1) * 8 + i8) * ROWB + (sel & 1) * 16);

    float acc[2][8][4];
#pragma unroll
    for (int mf = 0; mf < 2; mf++)
#pragma unroll
        for (int nf = 0; nf < 8; nf++)
#pragma unroll
            for (int q = 0; q < 4; q++) acc[mf][nf][q] = 0.0f;

    load_stage(0, 0);

    for (int kt = 0; kt < NKT; kt++) {
        if (kt + 1 < NKT) {
            load_stage(kt + 1, (kt + 1) & 1);
            asm volatile("cp.async.wait_group 1;" ::: "memory");
        } else {
            asm volatile("cp.async.wait_group 0;" ::: "memory");
        }
        __syncthreads();

        const uint32_t ahb = sb + (kt & 1) * STAGEB;
        const uint32_t alb = ahb + TILEB;
        const uint32_t bhb = ahb + 2 * TILEB;
        const uint32_t blb = ahb + 3 * TILEB;

#pragma unroll
        for (int kk = 0; kk < 4; kk++) {
            const uint32_t kb = kk * 32;
            uint32_t ah[2][4], al[2][4];
#pragma unroll
            for (int mf = 0; mf < 2; mf++) {
                LDMX4(ah[mf], ahb + a_off[mf] + kb);
                LDMX4(al[mf], alb + a_off[mf] + kb);
            }
            uint32_t bh[8][2], bl[8][2];
#pragma unroll
            for (int g = 0; g < 4; g++) {
                uint32_t r[4];
                LDMX4(r, bhb + b_off[g] + kb);
                bh[2 * g][0] = r[0]; bh[2 * g][1] = r[1];
                bh[2 * g + 1][0] = r[2]; bh[2 * g + 1][1] = r[3];
                LDMX4(r, blb + b_off[g] + kb);
                bl[2 * g][0] = r[0]; bl[2 * g][1] = r[1];
                bl[2 * g + 1][0] = r[2]; bl[2 * g + 1][1] = r[3];
            }
#pragma unroll
            for (int mf = 0; mf < 2; mf++)
#pragma unroll
                for (int nf = 0; nf < 8; nf++) {
                    MMA_BF16(acc[mf][nf], ah[mf], bh[nf]);
                    MMA_BF16(acc[mf][nf], ah[mf], bl[nf]);
                    MMA_BF16(acc[mf][nf], al[mf], bh[nf]);
                }
        }
        __syncthreads();
    }

#pragma unroll
    for (int mf = 0; mf < 2; mf++) {
        const int r0 = m0 + wm * 32 + mf * 16 + (lid >> 2);
#pragma unroll
        for (int nf = 0; nf < 8; nf++) {
            const int col = n0 + wn * 64 + nf * 8 + (lid & 3) * 2;
            const float b0 = bias[col], b1 = bias[col + 1];
            float2 v0 = make_float2(acc[mf][nf][0] + b0, acc[mf][nf][1] + b1);
            float2 v1 = make_float2(acc[mf][nf][2] + b0, acc[mf][nf][3] + b1);
            *(float2*)&C[(size_t)r0 * ldc + col]       = v0;
            *(float2*)&C[(size_t)(r0 + 8) * ldc + col] = v1;
        }
    }
}

// ===================================================================================
// k_gemm_f16: fp16 2-term GEMM for the output projection.
//   C[m][n] = sum_k Ahi[m][k]*(Bhi[n][k]+Blo[n][k]) + bias[n]
//   A single fp16 array (hidden states, exactly representable range);
//   B = w_out split fp16 hi/lo. 3 smem tiles/stage, 2 stages (111 KB).
// ===================================================================================
#define F_TILEB (128 * ROWB)            // 18432
#define F_STAGEB (3 * F_TILEB)          // 55296
#define SMEM_F16 (2 * F_STAGEB)         // 110592

__global__ __launch_bounds__(256, 1)
void k_gemm_f16(const half* __restrict__ Ahi,
                const half* __restrict__ Bhi, const half* __restrict__ Blo,
                const float* __restrict__ bias, float* __restrict__ C, int ldc)
{
    extern __shared__ char smbuf[];
    const uint32_t sb = smem_u32(smbuf);
    const int t = threadIdx.x, lid = t & 31, wid = t >> 5;
    const int m0 = blockIdx.x * BM;
    const int n0 = blockIdx.y * BN;
    const int wm = wid & 3;
    const int wn = wid >> 2;

    const int ldrow = t >> 3;
    const int ldc16 = t & 7;

    auto load_stage = [&](int kt, int stg) {
        const int kc = kt * BK;
        const uint32_t dbase = sb + stg * F_STAGEB;
#pragma unroll
        for (int T = 0; T < 3; T++) {
            const half* src = (T == 0) ? Ahi : (T == 1) ? Bhi : Blo;
            const int rbase = (T == 0) ? m0 : n0;
#pragma unroll
            for (int i = 0; i < 4; i++) {
                const int row = ldrow + i * 32;
                const uint32_t dst = dbase + T * F_TILEB + row * ROWB + ldc16 * 16;
                const void* g = src + (size_t)(rbase + row) * 1024 + kc + ldc16 * 8;
                CP_ASYNC16(dst, g);
            }
        }
        asm volatile("cp.async.commit_group;" ::: "memory");
    };

    const int sel = lid >> 3, i8 = lid & 7;
    uint32_t a_off[2], b_off[4];
#pragma unroll
    for (int mf = 0; mf < 2; mf++)
        a_off[mf] = (uint32_t)((wm * 32 + mf * 16 + (sel & 1) * 8 + i8) * ROWB + (sel >> 1) * 16);
#pragma unroll
    for (int g = 0; g < 4; g++)
        b_off[g] = (uint32_t)((wn * 64 + g * 16 + (sel >> 1) * 8 + i8) * ROWB + (sel & 1) * 16);

    float acc[2][8][4];
#pragma unroll
    for (int mf = 0; mf < 2; mf++)
#pragma unroll
        for (int nf = 0; nf < 8; nf++)
#pragma unroll
            for (int q = 0; q < 4; q++) acc[mf][nf][q] = 0.0f;

    load_stage(0, 0);

    for (int kt = 0; kt < NKT; kt++) {
        if (kt + 1 < NKT) {
            load_stage(kt + 1, (kt + 1) & 1);
            asm volatile("cp.async.wait_group 1;" ::: "memory");
        } else {
            asm volatile("cp.async.wait_group 0;" ::: "memory");
        }
        __syncthreads();

        const uint32_t ahb = sb + (kt & 1) * F_STAGEB;
        const uint32_t bhb = ahb + F_TILEB;
        const uint32_t blb = ahb + 2 * F_TILEB;

#pragma unroll
        for (int kk = 0; kk < 4; kk++) {
            const uint32_t kb = kk * 32;
            uint32_t ah[2][4];
#pragma unroll
            for (int mf = 0; mf < 2; mf++)
                LDMX4(ah[mf], ahb + a_off[mf] + kb);
            uint32_t bh[8][2], bl[8][2];
#pragma unroll
            for (int g = 0; g < 4; g++) {
                uint32_t r[4];
                LDMX4(r, bhb + b_off[g] + kb);
                bh[2 * g][0] = r[0]; bh[2 * g][1] = r[1];
                bh[2 * g + 1][0] = r[2]; bh[2 * g + 1][1] = r[3];
                LDMX4(r, blb + b_off[g] + kb);
                bl[2 * g][0] = r[0]; bl[2 * g][1] = r[1];
                bl[2 * g + 1][0] = r[2]; bl[2 * g + 1][1] = r[3];
            }
#pragma unroll
            for (int mf = 0; mf < 2; mf++)
#pragma unroll
                for (int nf = 0; nf < 8; nf++) {
                    MMA_F16(acc[mf][nf], ah[mf], bh[nf]);
                    MMA_F16(acc[mf][nf], ah[mf], bl[nf]);
                }
        }
        __syncthreads();
    }

#pragma unroll
    for (int mf = 0; mf < 2; mf++) {
        const int r0 = m0 + wm * 32 + mf * 16 + (lid >> 2);
#pragma unroll
        for (int nf = 0; nf < 8; nf++) {
            const int col = n0 + wn * 64 + nf * 8 + (lid & 3) * 2;
            const float b0 = bias[col], b1 = bias[col + 1];
            float2 v0 = make_float2(acc[mf][nf][0] + b0, acc[mf][nf][1] + b1);
            float2 v1 = make_float2(acc[mf][nf][2] + b0, acc[mf][nf][3] + b1);
            *(float2*)&C[(size_t)r0 * ldc + col]       = v0;
            *(float2*)&C[(size_t)(r0 + 8) * ldc + col] = v1;
        }
    }
}

// ===================================================================================
// k_scan: persistent fused LSTM scan (unchanged except fp16 a-write).
// ===================================================================================
#define WSTR 2064
#define ASTR 528
#define SM_WHI 0
#define SM_WLO 66048
#define SM_AB  132096
#define SM_GTS 199680
#define SMEM_SCAN 203904

__global__ __launch_bounds__(256, 1)
void k_scan(const float* __restrict__ w_hh, int ctx, int rpb)
{
    extern __shared__ char sm[];
    const uint32_t sb = smem_u32(sm);
    const int t = threadIdx.x, lid = t & 31, wid = t >> 5;
    const int cta = blockIdx.x;
    const int colbase = cta * 8;
    const int wm = wid & 1, wn = wid >> 1;

    for (int idx = t; idx < 32 * 256; idx += 256) {
        const int r = idx >> 8, c4 = idx & 255;
        const int grow = (r >> 3) * 1024 + colbase + (r & 7);
        float4 v = *(const float4*)(w_hh + (size_t)grow * 1024 + c4 * 4);
        __nv_bfloat16 h4[4], l4[4];
        split4(v, h4, l4);
        *(uint2*)(sm + SM_WHI + r * WSTR + c4 * 8) = *(uint2*)h4;
        *(uint2*)(sm + SM_WLO + r * WSTR + c4 * 8) = *(uint2*)l4;
    }

    {
        const int b = t >> 3, jj = t & 7;
        g_hb_hi[0][b * 1024 + colbase + jj] = __float2bfloat16(0.0f);
        g_hb_lo[0][b * 1024 + colbase + jj] = __float2bfloat16(0.0f);
    }
    __threadfence();
    __syncthreads();
    if (t == 0) {
        atomicAdd(&g_bar, 1u);
        while (ldacq(&g_bar) < 128u) __nanosleep(32);
    }
    __syncthreads();

    const int sel = lid >> 3, i8 = lid & 7;
    const uint32_t a_loff = (uint32_t)((wm * 16 + (sel & 1) * 8 + i8) * ASTR + (sel >> 1) * 16);
    const int l16 = lid & 15;
    const uint32_t b_off = sb + (uint32_t)((wn * 8 + (l16 & 7)) * WSTR + (l16 >> 3) * 16);

    const int ub = t >> 3, ujj = t & 7;
    const int ucol = colbase + ujj;
    float creg = 0.0f;
    float* gates_s = (float*)(sm + SM_GTS);

    for (int s = 0; s < SEQ; s++) {
        const int p = s & 1, np = p ^ 1;
        const __nv_bfloat16* hhi = g_hb_hi[p];
        const __nv_bfloat16* hlo = g_hb_lo[p];

        auto loadc = [&](int ch) {
            const uint32_t abase = sb + SM_AB + (uint32_t)((ch & 1) * 33792);
#pragma unroll
            for (int i = 0; i < 4; i++) {
                const int idx = t + i * 256, row = idx >> 5, c16 = idx & 31;
                CP_ASYNC16(abase + row * ASTR + c16 * 16,
                           hhi + row * 1024 + ch * 256 + c16 * 8);
                CP_ASYNC16(abase + 16896u + row * ASTR + c16 * 16,
                           hlo + row * 1024 + ch * 256 + c16 * 8);
            }
            asm volatile("cp.async.commit_group;" ::: "memory");
        };

        float acc[4] = {0.0f, 0.0f, 0.0f, 0.0f};
        loadc(0);
        for (int ch = 0; ch < 4; ch++) {
            if (ch < 3) { loadc(ch + 1); asm volatile("cp.async.wait_group 1;" ::: "memory"); }
            else        {                asm volatile("cp.async.wait_group 0;" ::: "memory"); }
            __syncthreads();
            const uint32_t abh = sb + SM_AB + (uint32_t)((ch & 1) * 33792) + a_loff;
            const uint32_t abl = abh + 16896u;
            const uint32_t wk = (uint32_t)(ch * 512);
#pragma unroll
            for (int k16 = 0; k16 < 16; k16++) {
                uint32_t ah[4], al[4], bh[2], bl[2];
                LDMX4(ah, abh + k16 * 32);
                LDMX4(al, abl + k16 * 32);
                LDMX2(bh, b_off + wk + k16 * 32);
                LDMX2(bl, b_off + 66048u + wk + k16 * 32);
                MMA_BF16(acc, ah, bh);
                MMA_BF16(acc, ah, bl);
                MMA_BF16(acc, al, bh);
            }
            __syncthreads();
        }

        {
            const int m = wm * 16 + (lid >> 2);
            const int n = wn * 8 + (lid & 3) * 2;
            gates_s[n * 33 + m]             = acc[0];
            gates_s[(n + 1) * 33 + m]       = acc[1];
            gates_s[n * 33 + m + 8]         = acc[2];
            gates_s[(n + 1) * 33 + m + 8]   = acc[3];
        }
        __syncthreads();

        {
            const float* xr = g_xg + (size_t)(s * 32 + ub) * GDIM + ucol;
            const float ipre = gates_s[(0  + ujj) * 33 + ub] + xr[0];
            const float fpre = gates_s[(8  + ujj) * 33 + ub] + xr[1024];
            const float gpre = gates_s[(16 + ujj) * 33 + ub] + xr[2048];
            const float opre = gates_s[(24 + ujj) * 33 + ub] + xr[3072];
            const float iv = sigmoidf_(ipre), fv = sigmoidf_(fpre);
            const float gv = tanhf(gpre),     ov = sigmoidf_(opre);
            creg = fv * creg + iv * gv;
            const float hv = ov * tanhf(creg);
            const __nv_bfloat16 hb = __float2bfloat16(hv);
            const __nv_bfloat16 lb = __float2bfloat16(hv - __bfloat162float(hb));
            g_hb_hi[np][ub * 1024 + ucol] = hb;
            g_hb_lo[np][ub * 1024 + ucol] = lb;
            if (s >= ctx) {
                const size_t ro = (size_t)(ub * rpb + (s - ctx)) * 1024 + ucol;
                g_af[ro] = __float2half(hv);
            }
        }
        __threadfence();
        __syncthreads();
        if (t == 0) {
            atomicAdd(&g_bar, 1u);
            const unsigned tgt = 128u * (unsigned)(s + 2);
            while (ldacq(&g_bar) < tgt) __nanosleep(32);
        }
        __syncthreads();
    }
}

// ===================================================================================
// Split / gather / bias / reset kernels
// ===================================================================================
__global__ void k_split(const float* __restrict__ src, __nv_bfloat16* __restrict__ hi,
                        __nv_bfloat16* __restrict__ lo, int n4)
{
    int i = blockIdx.x * blockDim.x + threadIdx.x;
    if (i >= n4) return;
    split4(((const float4*)src)[i], hi + i * 4, lo + i * 4);
}

__global__ void k_split_h(const float* __restrict__ src, half* __restrict__ hi,
                          half* __restrict__ lo, int n4)
{
    int i = blockIdx.x * blockDim.x + threadIdx.x;
    if (i >= n4) return;
    split4h(((const float4*)src)[i], hi + i * 4, lo + i * 4);
}

__global__ void k_split_gx(const int* __restrict__ ids, const float* __restrict__ emb)
{
    int m = blockIdx.x, t = threadIdx.x;
    int s = m >> 5, b = m & 31;
    const float* src = emb + (size_t)ids[b * SEQ + s] * IDIM;
    float4 v = ((const float4*)src)[t];
    split4(v, g_x_hi + (size_t)m * IDIM + t * 4, g_x_lo + (size_t)m * IDIM + t * 4);
}

__global__ void k_bsum(const float* __restrict__ b_ih, const float* __restrict__ b_hh)
{
    int i = blockIdx.x * blockDim.x + threadIdx.x;
    if (i < GDIM) g_bsum[i] = b_ih[i] + b_hh[i];
}

__global__ void k_reset() {
    if (threadIdx.x == 0 && blockIdx.x == 0) g_bar = 0;
}

// ===================================================================================
// kernel_launch
// ===================================================================================
extern "C" void kernel_launch(void* const* d_in, const int* in_sizes, int n_in,
                              void* d_out, int out_size)
{
    const int*   ids   = (const int*)  d_in[0];
    const float* emb   = (const float*)d_in[1];
    const float* w_ih  = (const float*)d_in[2];
    const float* w_hh  = (const float*)d_in[3];
    const float* b_ih  = (const float*)d_in[4];
    const float* b_hh  = (const float*)d_in[5];
    const float* w_out = (const float*)d_in[6];
    const float* b_out = (const float*)d_in[7];
    float* out = (float*)d_out;

    const int rows       = out_size / VOCAB;     // (S - ctx) * B = 2816
    const int rows_per_b = rows / BATCH;         // 88
    const int ctx        = SEQ - rows_per_b;     // 40

    cudaFuncSetAttribute(k_gemm_mma, cudaFuncAttributeMaxDynamicSharedMemorySize, SMEM_MMA);
    cudaFuncSetAttribute(k_gemm_f16, cudaFuncAttributeMaxDynamicSharedMemorySize, SMEM_F16);
    cudaFuncSetAttribute(k_scan,     cudaFuncAttributeMaxDynamicSharedMemorySize, SMEM_SCAN);

    __nv_bfloat16 *p_xhi, *p_xlo, *p_wihhi, *p_wihlo;
    half *p_wohi, *p_wolo, *p_af;
    float *p_bsum, *p_xg;
    cudaGetSymbolAddress((void**)&p_xhi,   g_x_hi);
    cudaGetSymbolAddress((void**)&p_xlo,   g_x_lo);
    cudaGetSymbolAddress((void**)&p_wihhi, g_wih_hi);
    cudaGetSymbolAddress((void**)&p_wihlo, g_wih_lo);
    cudaGetSymbolAddress((void**)&p_wohi,  g_wo_hi);
    cudaGetSymbolAddress((void**)&p_wolo,  g_wo_lo);
    cudaGetSymbolAddress((void**)&p_af,    g_af);
    cudaGetSymbolAddress((void**)&p_bsum,  g_bsum);
    cudaGetSymbolAddress((void**)&p_xg,    g_xg);

    // 0) reset barrier + biases + operand splits
    k_reset<<<1, 32>>>();
    k_bsum<<<16, 256>>>(b_ih, b_hh);
    k_split<<<(GDIM * IDIM / 4 + 255) / 256, 256>>>(w_ih, p_wihhi, p_wihlo, GDIM * IDIM / 4);
    k_split_gx<<<SEQ * BATCH, 256>>>(ids, emb);
    k_split_h<<<(VOCAB * HDIM / 4 + 255) / 256, 256>>>(w_out, p_wohi, p_wolo, VOCAB * HDIM / 4);

    // 1) x_gates = gather(emb) @ w_ih^T + (b_ih + b_hh)   — bf16x3 mma.sync
    k_gemm_mma<<<dim3(SEQ * BATCH / BM, GDIM / BN), 256, SMEM_MMA>>>(
        p_xhi, p_xlo, p_wihhi, p_wihlo, p_bsum, p_xg, GDIM);

    // 2) fused persistent recurrent scan
    k_scan<<<128, 256, SMEM_SCAN>>>(w_hh, ctx, rows_per_b);

    // 3) output projection — fp16 2-term mma.sync
    k_gemm_f16<<<dim3(rows / BM, VOCAB / BN), 256, SMEM_F16>>>(
        p_af, p_wohi, p_wolo, b_out, out, VOCAB);
}

// round 17
// speedup vs baseline: 3.7797x; 1.2933x over previous
#include <cuda_runtime.h>
#include <cuda_bf16.h>
#include <cuda_fp16.h>
#include <math.h>
#include <stdint.h>

// Problem constants (fixed-shape problem)
#define BATCH 32
#define SEQ   128
#define IDIM  1024
#define HDIM  1024
#define GDIM  4096   // 4*HDIM
#define VOCAB 32000

// ---------------- scratch (device globals; no cudaMalloc allowed) ----------------
__device__ float g_xg[SEQ * BATCH * GDIM];     // input gates (S,B,4H) : 64 MB
__device__ float g_bsum[GDIM];                 // b_ih + b_hh
__device__ unsigned g_bar;                     // grid barrier counter

// h state, double-buffered by step parity, stored as bf16 hi/lo
__device__ __align__(16) __nv_bfloat16 g_hb_hi[2][BATCH * HDIM];
__device__ __align__(16) __nv_bfloat16 g_hb_lo[2][BATCH * HDIM];

// bf16 hi/lo splits for the input GEMM (bf16x3)
__device__ __align__(16) __nv_bfloat16 g_x_hi[SEQ * BATCH * IDIM];   // gathered emb rows
__device__ __align__(16) __nv_bfloat16 g_x_lo[SEQ * BATCH * IDIM];
__device__ __align__(16) __nv_bfloat16 g_wih_hi[GDIM * IDIM];
__device__ __align__(16) __nv_bfloat16 g_wih_lo[GDIM * IDIM];

// fp16 operands for the output GEMM (single-term: fp16(h) * fp16(w_out))
__device__ __align__(16) half g_wo_hi[VOCAB * HDIM];                 // 65.5 MB
__device__ __align__(16) half g_af[SEQ * BATCH * HDIM];              // hs rows (fp16)

__device__ __forceinline__ float sigmoidf_(float x) { return 1.0f / (1.0f + expf(-x)); }

__device__ __forceinline__ uint32_t smem_u32(const void* p) {
    uint32_t a;
    asm("{ .reg .u64 t; cvta.to.shared.u64 t, %1; cvt.u32.u64 %0, t; }" : "=r"(a) : "l"(p));
    return a;
}
__device__ __forceinline__ unsigned ldacq(const unsigned* p) {
    unsigned v;
    asm volatile("ld.global.acquire.gpu.u32 %0, [%1];" : "=r"(v) : "l"(p));
    return v;
}

// ---------------- mma.sync / ldmatrix / cp.async (plain sm_103-legal) ----------------
#define LDMX4(r, addr)                                                                \
    asm volatile("ldmatrix.sync.aligned.m8n8.x4.shared.b16 {%0,%1,%2,%3}, [%4];"      \
        : "=r"((r)[0]), "=r"((r)[1]), "=r"((r)[2]), "=r"((r)[3]) : "r"(addr))

#define LDMX2(r, addr)                                                                \
    asm volatile("ldmatrix.sync.aligned.m8n8.x2.shared.b16 {%0,%1}, [%2];"            \
        : "=r"((r)[0]), "=r"((r)[1]) : "r"(addr))

#define MMA_BF16(c, a, b)                                                             \
    asm volatile("mma.sync.aligned.m16n8k16.row.col.f32.bf16.bf16.f32 "               \
        "{%0,%1,%2,%3}, {%4,%5,%6,%7}, {%8,%9}, {%0,%1,%2,%3};"                       \
        : "+f"((c)[0]), "+f"((c)[1]), "+f"((c)[2]), "+f"((c)[3])                      \
        : "r"((a)[0]), "r"((a)[1]), "r"((a)[2]), "r"((a)[3]),                         \
          "r"((b)[0]), "r"((b)[1]))

#define MMA_F16(c, a, b)                                                              \
    asm volatile("mma.sync.aligned.m16n8k16.row.col.f32.f16.f16.f32 "                 \
        "{%0,%1,%2,%3}, {%4,%5,%6,%7}, {%8,%9}, {%0,%1,%2,%3};"                       \
        : "+f"((c)[0]), "+f"((c)[1]), "+f"((c)[2]), "+f"((c)[3])                      \
        : "r"((a)[0]), "r"((a)[1]), "r"((a)[2]), "r"((a)[3]),                         \
          "r"((b)[0]), "r"((b)[1]))

#define CP_ASYNC16(dst, src)                                                          \
    asm volatile("cp.async.cg.shared.global [%0], [%1], 16;" :: "r"(dst), "l"(src))

// ---------------- bf16 hi/lo split helper ----------------
__device__ __forceinline__ void split4(float4 v, __nv_bfloat16* hi, __nv_bfloat16* lo) {
    __nv_bfloat16 h0 = __float2bfloat16(v.x), h1 = __float2bfloat16(v.y);
    __nv_bfloat16 h2 = __float2bfloat16(v.z), h3 = __float2bfloat16(v.w);
    __nv_bfloat16 l0 = __float2bfloat16(v.x - __bfloat162float(h0));
    __nv_bfloat16 l1 = __float2bfloat16(v.y - __bfloat162float(h1));
    __nv_bfloat16 l2 = __float2bfloat16(v.z - __bfloat162float(h2));
    __nv_bfloat16 l3 = __float2bfloat16(v.w - __bfloat162float(h3));
    ((__nv_bfloat162*)hi)[0] = __halves2bfloat162(h0, h1);
    ((__nv_bfloat162*)hi)[1] = __halves2bfloat162(h2, h3);
    ((__nv_bfloat162*)lo)[0] = __halves2bfloat162(l0, l1);
    ((__nv_bfloat162*)lo)[1] = __halves2bfloat162(l2, l3);
}

// ===================================================================================
// k_gemm_mma: bf16x3 GEMM (unchanged, used for x_gates)
// ===================================================================================
#define BM 128
#define BN 128
#define BK 64
#define ROWB 144
#define TILEB (128 * ROWB)
#define STAGEB (4 * TILEB)
#define SMEM_MMA (2 * STAGEB)
#define NKT (1024 / BK)

__global__ __launch_bounds__(256, 1)
void k_gemm_mma(const __nv_bfloat16* __restrict__ Ahi, const __nv_bfloat16* __restrict__ Alo,
                const __nv_bfloat16* __restrict__ Bhi, const __nv_bfloat16* __restrict__ Blo,
                const float* __restrict__ bias, float* __restrict__ C, int ldc)
{
    extern __shared__ char smbuf[];
    const uint32_t sb = smem_u32(smbuf);
    const int t = threadIdx.x, lid = t & 31, wid = t >> 5;
    const int m0 = blockIdx.x * BM;
    const int n0 = blockIdx.y * BN;
    const int wm = wid & 3;
    const int wn = wid >> 2;

    const int ldrow = t >> 3;
    const int ldc16 = t & 7;

    auto load_stage = [&](int kt, int stg) {
        const int kc = kt * BK;
        const uint32_t dbase = sb + stg * STAGEB;
#pragma unroll
        for (int T = 0; T < 4; T++) {
            const __nv_bfloat16* src = (T == 0) ? Ahi : (T == 1) ? Alo : (T == 2) ? Bhi : Blo;
            const int rbase = (T < 2) ? m0 : n0;
#pragma unroll
            for (int i = 0; i < 4; i++) {
                const int row = ldrow + i * 32;
                const uint32_t dst = dbase + T * TILEB + row * ROWB + ldc16 * 16;
                const void* g = src + (size_t)(rbase + row) * 1024 + kc + ldc16 * 8;
                CP_ASYNC16(dst, g);
            }
        }
        asm volatile("cp.async.commit_group;" ::: "memory");
    };

    const int sel = lid >> 3, i8 = lid & 7;
    uint32_t a_off[2], b_off[4];
#pragma unroll
    for (int mf = 0; mf < 2; mf++)
        a_off[mf] = (uint32_t)((wm * 32 + mf * 16 + (sel & 1) * 8 + i8) * ROWB + (sel >> 1) * 16);
#pragma unroll
    for (int g = 0; g < 4; g++)
        b_off[g] = (uint32_t)((wn * 64 + g * 16 + (sel >> 1) * 8 + i8) * ROWB + (sel & 1) * 16);

    float acc[2][8][4];
#pragma unroll
    for (int mf = 0; mf < 2; mf++)
#pragma unroll
        for (int nf = 0; nf < 8; nf++)
#pragma unroll
            for (int q = 0; q < 4; q++) acc[mf][nf][q] = 0.0f;

    load_stage(0, 0);

    for (int kt = 0; kt < NKT; kt++) {
        if (kt + 1 < NKT) {
            load_stage(kt + 1, (kt + 1) & 1);
            asm volatile("cp.async.wait_group 1;" ::: "memory");
        } else {
            asm volatile("cp.async.wait_group 0;" ::: "memory");
        }
        __syncthreads();

        const uint32_t ahb = sb + (kt & 1) * STAGEB;
        const uint32_t alb = ahb + TILEB;
        const uint32_t bhb = ahb + 2 * TILEB;
        const uint32_t blb = ahb + 3 * TILEB;

#pragma unroll
        for (int kk = 0; kk < 4; kk++) {
            const uint32_t kb = kk * 32;
            uint32_t ah[2][4], al[2][4];
#pragma unroll
            for (int mf = 0; mf < 2; mf++) {
                LDMX4(ah[mf], ahb + a_off[mf] + kb);
                LDMX4(al[mf], alb + a_off[mf] + kb);
            }
            uint32_t bh[8][2], bl[8][2];
#pragma unroll
            for (int g = 0; g < 4; g++) {
                uint32_t r[4];
                LDMX4(r, bhb + b_off[g] + kb);
                bh[2 * g][0] = r[0]; bh[2 * g][1] = r[1];
                bh[2 * g + 1][0] = r[2]; bh[2 * g + 1][1] = r[3];
                LDMX4(r, blb + b_off[g] + kb);
                bl[2 * g][0] = r[0]; bl[2 * g][1] = r[1];
                bl[2 * g + 1][0] = r[2]; bl[2 * g + 1][1] = r[3];
            }
#pragma unroll
            for (int mf = 0; mf < 2; mf++)
#pragma unroll
                for (int nf = 0; nf < 8; nf++) {
                    MMA_BF16(acc[mf][nf], ah[mf], bh[nf]);
                    MMA_BF16(acc[mf][nf], ah[mf], bl[nf]);
                    MMA_BF16(acc[mf][nf], al[mf], bh[nf]);
                }
        }
        __syncthreads();
    }

#pragma unroll
    for (int mf = 0; mf < 2; mf++) {
        const int r0 = m0 + wm * 32 + mf * 16 + (lid >> 2);
#pragma unroll
        for (int nf = 0; nf < 8; nf++) {
            const int col = n0 + wn * 64 + nf * 8 + (lid & 3) * 2;
            const float b0 = bias[col], b1 = bias[col + 1];
            float2 v0 = make_float2(acc[mf][nf][0] + b0, acc[mf][nf][1] + b1);
            float2 v1 = make_float2(acc[mf][nf][2] + b0, acc[mf][nf][3] + b1);
            *(float2*)&C[(size_t)r0 * ldc + col]       = v0;
            *(float2*)&C[(size_t)(r0 + 8) * ldc + col] = v1;
        }
    }
}

// ===================================================================================
// k_gemm_f16: single-term fp16 GEMM for the output projection.
//   C[m][n] = sum_k Ahi[m][k]*Bhi[n][k] + bias[n]
//   2 smem tiles/stage (A, B), 2 stages (73.7 KB) -> 2 CTAs/SM co-resident.
// ===================================================================================
#define F_TILEB (128 * ROWB)            // 18432
#define F_STAGEB (2 * F_TILEB)          // 36864
#define SMEM_F16 (2 * F_STAGEB)         // 73728

__global__ __launch_bounds__(256, 2)
void k_gemm_f16(const half* __restrict__ Ahi, const half* __restrict__ Bhi,
                const float* __restrict__ bias, float* __restrict__ C, int ldc)
{
    extern __shared__ char smbuf[];
    const uint32_t sb = smem_u32(smbuf);
    const int t = threadIdx.x, lid = t & 31, wid = t >> 5;
    const int m0 = blockIdx.x * BM;
    const int n0 = blockIdx.y * BN;
    const int wm = wid & 3;
    const int wn = wid >> 2;

    const int ldrow = t >> 3;
    const int ldc16 = t & 7;

    auto load_stage = [&](int kt, int stg) {
        const int kc = kt * BK;
        const uint32_t dbase = sb + stg * F_STAGEB;
#pragma unroll
        for (int T = 0; T < 2; T++) {
            const half* src = (T == 0) ? Ahi : Bhi;
            const int rbase = (T == 0) ? m0 : n0;
#pragma unroll
            for (int i = 0; i < 4; i++) {
                const int row = ldrow + i * 32;
                const uint32_t dst = dbase + T * F_TILEB + row * ROWB + ldc16 * 16;
                const void* g = src + (size_t)(rbase + row) * 1024 + kc + ldc16 * 8;
                CP_ASYNC16(dst, g);
            }
        }
        asm volatile("cp.async.commit_group;" ::: "memory");
    };

    const int sel = lid >> 3, i8 = lid & 7;
    uint32_t a_off[2], b_off[4];
#pragma unroll
    for (int mf = 0; mf < 2; mf++)
        a_off[mf] = (uint32_t)((wm * 32 + mf * 16 + (sel & 1) * 8 + i8) * ROWB + (sel >> 1) * 16);
#pragma unroll
    for (int g = 0; g < 4; g++)
        b_off[g] = (uint32_t)((wn * 64 + g * 16 + (sel >> 1) * 8 + i8) * ROWB + (sel & 1) * 16);

    float acc[2][8][4];
#pragma unroll
    for (int mf = 0; mf < 2; mf++)
#pragma unroll
        for (int nf = 0; nf < 8; nf++)
#pragma unroll
            for (int q = 0; q < 4; q++) acc[mf][nf][q] = 0.0f;

    load_stage(0, 0);

    for (int kt = 0; kt < NKT; kt++) {
        if (kt + 1 < NKT) {
            load_stage(kt + 1, (kt + 1) & 1);
            asm volatile("cp.async.wait_group 1;" ::: "memory");
        } else {
            asm volatile("cp.async.wait_group 0;" ::: "memory");
        }
        __syncthreads();

        const uint32_t ahb = sb + (kt & 1) * F_STAGEB;
        const uint32_t bhb = ahb + F_TILEB;

#pragma unroll
        for (int kk = 0; kk < 4; kk++) {
            const uint32_t kb = kk * 32;
            uint32_t ah[2][4];
#pragma unroll
            for (int mf = 0; mf < 2; mf++)
                LDMX4(ah[mf], ahb + a_off[mf] + kb);
            uint32_t bh[8][2];
#pragma unroll
            for (int g = 0; g < 4; g++) {
                uint32_t r[4];
                LDMX4(r, bhb + b_off[g] + kb);
                bh[2 * g][0] = r[0]; bh[2 * g][1] = r[1];
                bh[2 * g + 1][0] = r[2]; bh[2 * g + 1][1] = r[3];
            }
#pragma unroll
            for (int mf = 0; mf < 2; mf++)
#pragma unroll
                for (int nf = 0; nf < 8; nf++)
                    MMA_F16(acc[mf][nf], ah[mf], bh[nf]);
        }
        __syncthreads();
    }

#pragma unroll
    for (int mf = 0; mf < 2; mf++) {
        const int r0 = m0 + wm * 32 + mf * 16 + (lid >> 2);
#pragma unroll
        for (int nf = 0; nf < 8; nf++) {
            const int col = n0 + wn * 64 + nf * 8 + (lid & 3) * 2;
            const float b0 = bias[col], b1 = bias[col + 1];
            float2 v0 = make_float2(acc[mf][nf][0] + b0, acc[mf][nf][1] + b1);
            float2 v1 = make_float2(acc[mf][nf][2] + b0, acc[mf][nf][3] + b1);
            *(float2*)&C[(size_t)r0 * ldc + col]       = v0;
            *(float2*)&C[(size_t)(r0 + 8) * ldc + col] = v1;
        }
    }
}

// ===================================================================================
// k_scan: persistent fused LSTM scan (unchanged).
// ===================================================================================
#define WSTR 2064
#define ASTR 528
#define SM_WHI 0
#define SM_WLO 66048
#define SM_AB  132096
#define SM_GTS 199680
#define SMEM_SCAN 203904

__global__ __launch_bounds__(256, 1)
void k_scan(const float* __restrict__ w_hh, int ctx, int rpb)
{
    extern __shared__ char sm[];
    const uint32_t sb = smem_u32(sm);
    const int t = threadIdx.x, lid = t & 31, wid = t >> 5;
    const int cta = blockIdx.x;
    const int colbase = cta * 8;
    const int wm = wid & 1, wn = wid >> 1;

    for (int idx = t; idx < 32 * 256; idx += 256) {
        const int r = idx >> 8, c4 = idx & 255;
        const int grow = (r >> 3) * 1024 + colbase + (r & 7);
        float4 v = *(const float4*)(w_hh + (size_t)grow * 1024 + c4 * 4);
        __nv_bfloat16 h4[4], l4[4];
        split4(v, h4, l4);
        *(uint2*)(sm + SM_WHI + r * WSTR + c4 * 8) = *(uint2*)h4;
        *(uint2*)(sm + SM_WLO + r * WSTR + c4 * 8) = *(uint2*)l4;
    }

    {
        const int b = t >> 3, jj = t & 7;
        g_hb_hi[0][b * 1024 + colbase + jj] = __float2bfloat16(0.0f);
        g_hb_lo[0][b * 1024 + colbase + jj] = __float2bfloat16(0.0f);
    }
    __threadfence();
    __syncthreads();
    if (t == 0) {
        atomicAdd(&g_bar, 1u);
        while (ldacq(&g_bar) < 128u) __nanosleep(32);
    }
    __syncthreads();

    const int sel = lid >> 3, i8 = lid & 7;
    const uint32_t a_loff = (uint32_t)((wm * 16 + (sel & 1) * 8 + i8) * ASTR + (sel >> 1) * 16);
    const int l16 = lid & 15;
    const uint32_t b_off = sb + (uint32_t)((wn * 8 + (l16 & 7)) * WSTR + (l16 >> 3) * 16);

    const int ub = t >> 3, ujj = t & 7;
    const int ucol = colbase + ujj;
    float creg = 0.0f;
    float* gates_s = (float*)(sm + SM_GTS);

    for (int s = 0; s < SEQ; s++) {
        const int p = s & 1, np = p ^ 1;
        const __nv_bfloat16* hhi = g_hb_hi[p];
        const __nv_bfloat16* hlo = g_hb_lo[p];

        auto loadc = [&](int ch) {
            const uint32_t abase = sb + SM_AB + (uint32_t)((ch & 1) * 33792);
#pragma unroll
            for (int i = 0; i < 4; i++) {
                const int idx = t + i * 256, row = idx >> 5, c16 = idx & 31;
                CP_ASYNC16(abase + row * ASTR + c16 * 16,
                           hhi + row * 1024 + ch * 256 + c16 * 8);
                CP_ASYNC16(abase + 16896u + row * ASTR + c16 * 16,
                           hlo + row * 1024 + ch * 256 + c16 * 8);
            }
            asm volatile("cp.async.commit_group;" ::: "memory");
        };

        float acc[4] = {0.0f, 0.0f, 0.0f, 0.0f};
        loadc(0);
        for (int ch = 0; ch < 4; ch++) {
            if (ch < 3) { loadc(ch + 1); asm volatile("cp.async.wait_group 1;" ::: "memory"); }
            else        {                asm volatile("cp.async.wait_group 0;" ::: "memory"); }
            __syncthreads();
            const uint32_t abh = sb + SM_AB + (uint32_t)((ch & 1) * 33792) + a_loff;
            const uint32_t abl = abh + 16896u;
            const uint32_t wk = (uint32_t)(ch * 512);
#pragma unroll
            for (int k16 = 0; k16 < 16; k16++) {
                uint32_t ah[4], al[4], bh[2], bl[2];
                LDMX4(ah, abh + k16 * 32);
                LDMX4(al, abl + k16 * 32);
                LDMX2(bh, b_off + wk + k16 * 32);
                LDMX2(bl, b_off + 66048u + wk + k16 * 32);
                MMA_BF16(acc, ah, bh);
                MMA_BF16(acc, ah, bl);
                MMA_BF16(acc, al, bh);
            }
            __syncthreads();
        }

        {
            const int m = wm * 16 + (lid >> 2);
            const int n = wn * 8 + (lid & 3) * 2;
            gates_s[n * 33 + m]             = acc[0];
            gates_s[(n + 1) * 33 + m]       = acc[1];
            gates_s[n * 33 + m + 8]         = acc[2];
            gates_s[(n + 1) * 33 + m + 8]   = acc[3];
        }
        __syncthreads();

        {
            const float* xr = g_xg + (size_t)(s * 32 + ub) * GDIM + ucol;
            const float ipre = gates_s[(0  + ujj) * 33 + ub] + xr[0];
            const float fpre = gates_s[(8  + ujj) * 33 + ub] + xr[1024];
            const float gpre = gates_s[(16 + ujj) * 33 + ub] + xr[2048];
            const float opre = gates_s[(24 + ujj) * 33 + ub] + xr[3072];
            const float iv = sigmoidf_(ipre), fv = sigmoidf_(fpre);
            const float gv = tanhf(gpre),     ov = sigmoidf_(opre);
            creg = fv * creg + iv * gv;
            const float hv = ov * tanhf(creg);
            const __nv_bfloat16 hb = __float2bfloat16(hv);
            const __nv_bfloat16 lb = __float2bfloat16(hv - __bfloat162float(hb));
            g_hb_hi[np][ub * 1024 + ucol] = hb;
            g_hb_lo[np][ub * 1024 + ucol] = lb;
            if (s >= ctx) {
                const size_t ro = (size_t)(ub * rpb + (s - ctx)) * 1024 + ucol;
                g_af[ro] = __float2half(hv);
            }
        }
        __threadfence();
        __syncthreads();
        if (t == 0) {
            atomicAdd(&g_bar, 1u);
            const unsigned tgt = 128u * (unsigned)(s + 2);
            while (ldacq(&g_bar) < tgt) __nanosleep(32);
        }
        __syncthreads();
    }
}

// ===================================================================================
// Split / convert / gather / bias / reset kernels
// ===================================================================================
__global__ void k_split(const float* __restrict__ src, __nv_bfloat16* __restrict__ hi,
                        __nv_bfloat16* __restrict__ lo, int n4)
{
    int i = blockIdx.x * blockDim.x + threadIdx.x;
    if (i >= n4) return;
    split4(((const float4*)src)[i], hi + i * 4, lo + i * 4);
}

__global__ void k_tohalf(const float* __restrict__ src, half* __restrict__ dst, int n4)
{
    int i = blockIdx.x * blockDim.x + threadIdx.x;
    if (i >= n4) return;
    float4 v = ((const float4*)src)[i];
    half2 a = __halves2half2(__float2half(v.x), __float2half(v.y));
    half2 b = __halves2half2(__float2half(v.z), __float2half(v.w));
    ((half2*)(dst + i * 4))[0] = a;
    ((half2*)(dst + i * 4))[1] = b;
}

__global__ void k_split_gx(const int* __restrict__ ids, const float* __restrict__ emb)
{
    int m = blockIdx.x, t = threadIdx.x;
    int s = m >> 5, b = m & 31;
    const float* src = emb + (size_t)ids[b * SEQ + s] * IDIM;
    float4 v = ((const float4*)src)[t];
    split4(v, g_x_hi + (size_t)m * IDIM + t * 4, g_x_lo + (size_t)m * IDIM + t * 4);
}

__global__ void k_bsum(const float* __restrict__ b_ih, const float* __restrict__ b_hh)
{
    int i = blockIdx.x * blockDim.x + threadIdx.x;
    if (i < GDIM) g_bsum[i] = b_ih[i] + b_hh[i];
}

__global__ void k_reset() {
    if (threadIdx.x == 0 && blockIdx.x == 0) g_bar = 0;
}

// ===================================================================================
// kernel_launch
// ===================================================================================
extern "C" void kernel_launch(void* const* d_in, const int* in_sizes, int n_in,
                              void* d_out, int out_size)
{
    const int*   ids   = (const int*)  d_in[0];
    const float* emb   = (const float*)d_in[1];
    const float* w_ih  = (const float*)d_in[2];
    const float* w_hh  = (const float*)d_in[3];
    const float* b_ih  = (const float*)d_in[4];
    const float* b_hh  = (const float*)d_in[5];
    const float* w_out = (const float*)d_in[6];
    const float* b_out = (const float*)d_in[7];
    float* out = (float*)d_out;

    const int rows       = out_size / VOCAB;     // (S - ctx) * B = 2816
    const int rows_per_b = rows / BATCH;         // 88
    const int ctx        = SEQ - rows_per_b;     // 40

    cudaFuncSetAttribute(k_gemm_mma, cudaFuncAttributeMaxDynamicSharedMemorySize, SMEM_MMA);
    cudaFuncSetAttribute(k_gemm_f16, cudaFuncAttributeMaxDynamicSharedMemorySize, SMEM_F16);
    cudaFuncSetAttribute(k_scan,     cudaFuncAttributeMaxDynamicSharedMemorySize, SMEM_SCAN);

    __nv_bfloat16 *p_xhi, *p_xlo, *p_wihhi, *p_wihlo;
    half *p_wohi, *p_af;
    float *p_bsum, *p_xg;
    cudaGetSymbolAddress((void**)&p_xhi,   g_x_hi);
    cudaGetSymbolAddress((void**)&p_xlo,   g_x_lo);
    cudaGetSymbolAddress((void**)&p_wihhi, g_wih_hi);
    cudaGetSymbolAddress((void**)&p_wihlo, g_wih_lo);
    cudaGetSymbolAddress((void**)&p_wohi,  g_wo_hi);
    cudaGetSymbolAddress((void**)&p_af,    g_af);
    cudaGetSymbolAddress((void**)&p_bsum,  g_bsum);
    cudaGetSymbolAddress((void**)&p_xg,    g_xg);

    // 0) reset barrier + biases + operand splits/conversions
    k_reset<<<1, 32>>>();
    k_bsum<<<16, 256>>>(b_ih, b_hh);
    k_split<<<(GDIM * IDIM / 4 + 255) / 256, 256>>>(w_ih, p_wihhi, p_wihlo, GDIM * IDIM / 4);
    k_split_gx<<<SEQ * BATCH, 256>>>(ids, emb);
    k_tohalf<<<(VOCAB * HDIM / 4 + 255) / 256, 256>>>(w_out, p_wohi, VOCAB * HDIM / 4);

    // 1) x_gates = gather(emb) @ w_ih^T + (b_ih + b_hh)   — bf16x3 mma.sync
    k_gemm_mma<<<dim3(SEQ * BATCH / BM, GDIM / BN), 256, SMEM_MMA>>>(
        p_xhi, p_xlo, p_wihhi, p_wihlo, p_bsum, p_xg, GDIM);

    // 2) fused persistent recurrent scan
    k_scan<<<128, 256, SMEM_SCAN>>>(w_hh, ctx, rows_per_b);

    // 3) output projection — single-term fp16 mma.sync, 2 CTAs/SM
    k_gemm_f16<<<dim3(rows / BM, VOCAB / BN), 256, SMEM_F16>>>(
        p_af, p_wohi, b_out, out, VOCAB);
}